// round 11
// baseline (speedup 1.0000x reference)
#include <cuda_runtime.h>
#include <cuda_fp16.h>
#include <cstdint>
#include <cstddef>

#define FIN   256
#define HID   128
#define OUTD  64
#define MAXN  50176
#define MAXE  800000
#define SCAN_B 256
#define MAXBLK 256

__device__ __align__(16) __half g_xh[(size_t)MAXN * FIN];  // fp16 input features
__device__ __align__(16) __half g_T[(size_t)MAXN * HID];   // post-GEMM features
__device__ __align__(16) __half g_G1[(size_t)MAXN * HID];  // aggregated (fp16)
__device__ __align__(16) __half g_G2[(size_t)MAXN * HID];
__device__ __align__(16) __half g_W0t[HID * FIN];          // transposed fp16 weights
__device__ __align__(16) __half g_W1t[HID * HID];
__device__ __align__(16) __half g_W2t[HID * HID];
__device__ __align__(16) __half g_Wlt[OUTD * HID];
__device__ float  g_dinv[MAXN];
__device__ int    g_cnt[MAXN];
__device__ int    g_offs[MAXN];
__device__ int    g_flags[MAXBLK];
__device__ int    g_aggv[MAXBLK];
__device__ int    g_prefv[MAXBLK];
__device__ int    g_ssrc[MAXE];
__device__ int    g_rank[MAXE];

// ---------------------------------------------------------------------------
// PTX helpers
// ---------------------------------------------------------------------------
__device__ __forceinline__ void cp_async16(void* smem_dst, const void* gmem_src) {
    uint32_t s = (uint32_t)__cvta_generic_to_shared(smem_dst);
    asm volatile("cp.async.cg.shared.global [%0], [%1], 16;\n" :: "r"(s), "l"(gmem_src));
}
__device__ __forceinline__ void cp_commit() {
    asm volatile("cp.async.commit_group;\n");
}
template<int N>
__device__ __forceinline__ void cp_wait() {
    asm volatile("cp.async.wait_group %0;\n" :: "n"(N));
}
__device__ __forceinline__ void mma_f16(float c[4], const uint32_t a[4],
                                        uint32_t b0, uint32_t b1) {
    asm volatile(
        "mma.sync.aligned.m16n8k16.row.col.f32.f16.f16.f32 "
        "{%0,%1,%2,%3}, {%4,%5,%6,%7}, {%8,%9}, {%0,%1,%2,%3};"
        : "+f"(c[0]), "+f"(c[1]), "+f"(c[2]), "+f"(c[3])
        : "r"(a[0]), "r"(a[1]), "r"(a[2]), "r"(a[3]), "r"(b0), "r"(b1));
}
// accumulate 8 halfs (one uint4) scaled by nr into acc[8]
__device__ __forceinline__ void accum_row8(float acc[8], const __half* __restrict__ T,
                                           int row, int l16, float nr) {
    uint4 u = *reinterpret_cast<const uint4*>(T + (size_t)row * HID + l16 * 8);
    const __half2* hp = reinterpret_cast<const __half2*>(&u);
    #pragma unroll
    for (int q = 0; q < 4; q++) {
        float2 f = __half22float2(hp[q]);
        acc[2*q]   += nr * f.x;
        acc[2*q+1] += nr * f.y;
    }
}

// ---------------------------------------------------------------------------
// Prep: zero cnt/flags, init out, convert x -> fp16, convert/transpose weights
// ---------------------------------------------------------------------------
__global__ void prep_kernel(const float* __restrict__ x,
                            const float* __restrict__ W0,
                            const float* __restrict__ W1,
                            const float* __restrict__ W2,
                            const float* __restrict__ Wl,
                            __half* __restrict__ xh,
                            __half* __restrict__ W0t,
                            __half* __restrict__ W1t,
                            __half* __restrict__ W2t,
                            __half* __restrict__ Wlt,
                            int* __restrict__ cnt, int* __restrict__ flags,
                            float* __restrict__ out, int n) {
    int t = blockIdx.x * blockDim.x + threadIdx.x;
    // x -> fp16, 8 elements per thread
    int totalx = n * FIN / 8;
    if (t < totalx) {
        const float4* xp = reinterpret_cast<const float4*>(x) + (size_t)t * 2;
        float4 a = xp[0], b = xp[1];
        uint4 u;
        __half2* hp = reinterpret_cast<__half2*>(&u);
        hp[0] = __float22half2_rn(make_float2(a.x, a.y));
        hp[1] = __float22half2_rn(make_float2(a.z, a.w));
        hp[2] = __float22half2_rn(make_float2(b.x, b.y));
        hp[3] = __float22half2_rn(make_float2(b.z, b.w));
        *(reinterpret_cast<uint4*>(xh) + t) = u;
    }
    if (t < n) cnt[t] = 0;
    if (t < MAXBLK) flags[t] = 0;
    if (t < OUTD) out[t] = __int_as_float(0xFF800000);
    if (t < FIN * HID) {            // W0 [256][128] -> W0t [128][256]
        int k = t / HID, n2 = t % HID;
        W0t[n2 * FIN + k] = __float2half(W0[t]);
    }
    if (t < HID * HID) {
        int k = t / HID, n2 = t % HID;
        W1t[n2 * HID + k] = __float2half(W1[t]);
        W2t[n2 * HID + k] = __float2half(W2[t]);
    }
    if (t < HID * OUTD) {
        int k = t / OUTD, n2 = t % OUTD;
        Wlt[n2 * HID + k] = __float2half(Wl[t]);
    }
}

// ---------------------------------------------------------------------------
// CSR build: histogram(+rank) -> fused single-pass scan (+dinv) -> rank-scatter
// ---------------------------------------------------------------------------
__global__ void hist_kernel(const int* __restrict__ ei, int* cnt, int* rank, int E) {
    int e = blockIdx.x * blockDim.x + threadIdx.x;
    if (e < E) rank[e] = atomicAdd(&cnt[ei[E + e]], 1);
}

// decoupled-lookback exclusive scan of cnt -> offs; also writes dinv
__global__ void scan_fused_kernel(const int* __restrict__ cnt, int* offs,
                                  float* dinv, int* flags, int* aggv,
                                  int* prefv, int n) {
    __shared__ int sm[SCAN_B];
    __shared__ int s_base;
    int b = blockIdx.x;
    int i = b * SCAN_B + threadIdx.x;
    int v = (i < n) ? cnt[i] : 0;
    sm[threadIdx.x] = v;
    __syncthreads();
    #pragma unroll
    for (int o = 1; o < SCAN_B; o <<= 1) {
        int y = (threadIdx.x >= o) ? sm[threadIdx.x - o] : 0;
        __syncthreads();
        sm[threadIdx.x] += y;
        __syncthreads();
    }
    if (threadIdx.x == 0) {
        int total = sm[SCAN_B - 1];
        if (b == 0) {
            prefv[0] = total;
            __threadfence();
            atomicExch(&flags[0], 2);
            s_base = 0;
        } else {
            aggv[b] = total;
            __threadfence();
            atomicExch(&flags[b], 1);
            int base = 0;
            for (int j = b - 1; j >= 0; j--) {
                int f;
                do { f = atomicAdd(&flags[j], 0); } while (f == 0);
                if (f == 2) { base += prefv[j]; break; }
                base += aggv[j];
            }
            prefv[b] = base + total;
            __threadfence();
            atomicExch(&flags[b], 2);
            s_base = base;
        }
    }
    __syncthreads();
    if (i < n) {
        offs[i] = s_base + sm[threadIdx.x] - v;
        dinv[i] = rsqrtf((float)(v + 1));
    }
}

__global__ void scatter_edges_kernel(const int* __restrict__ ei,
                                     const int* __restrict__ offs,
                                     const int* __restrict__ rank,
                                     int* ssrc, int E) {
    int e = blockIdx.x * blockDim.x + threadIdx.x;
    if (e < E) {
        ssrc[offs[ei[E + e]] + rank[e]] = ei[e];
    }
}

// ---------------------------------------------------------------------------
// FP16 tensor-core GEMM core. BK=32 halfs, fp16 A + transposed fp16 W.
//   As[128][40] halfs (pad 40 -> conflict-free), Ws[BN][40] halfs (n-major)
// ---------------------------------------------------------------------------
#define HPAD 40

template<int BN, int K>
struct HCore {
    static constexpr int NTN = (BN / 2) / 8;

    static __device__ __forceinline__
    void loadA(__half (*As)[HPAD], const __half* __restrict__ A,
               int rowBase, int kt, int n, int tid) {
        #pragma unroll
        for (int i = 0; i < 2; i++) {
            int ch  = i * 256 + tid;          // 512 chunks: 128 rows x 4
            int row = ch >> 2;
            int cin = (ch & 3) * 8;           // half offset
            int grow = rowBase + row;
            if (grow >= n) grow = n - 1;
            cp_async16(&As[row][cin], A + (size_t)grow * K + kt + cin);
        }
    }
    static __device__ __forceinline__
    void loadW(__half (*Ws)[HPAD], const __half* __restrict__ Wt, int kt, int tid) {
        constexpr int NCH = BN * 4;           // 4 chunks per n-row
        #pragma unroll
        for (int i = 0; i < NCH / 256; i++) {
            int ch  = i * 256 + tid;
            int nn  = ch >> 2;
            int cin = (ch & 3) * 8;
            cp_async16(&Ws[nn][cin], Wt + (size_t)nn * K + kt + cin);
        }
    }
    static __device__ __forceinline__
    void compute(const __half (*As)[HPAD], const __half (*Ws)[HPAD],
                 float acc[2][NTN][4], int m0, int n0, int lane) {
        const int gid = lane >> 2;
        const int tig = lane & 3;
        #pragma unroll
        for (int kk = 0; kk < 32; kk += 16) {
            uint32_t a[2][4];
            #pragma unroll
            for (int mt = 0; mt < 2; mt++) {
                int r = m0 + mt * 16 + gid;
                int c = kk + tig * 2;
                a[mt][0] = *reinterpret_cast<const uint32_t*>(&As[r    ][c    ]);
                a[mt][1] = *reinterpret_cast<const uint32_t*>(&As[r + 8][c    ]);
                a[mt][2] = *reinterpret_cast<const uint32_t*>(&As[r    ][c + 8]);
                a[mt][3] = *reinterpret_cast<const uint32_t*>(&As[r + 8][c + 8]);
            }
            #pragma unroll
            for (int nt = 0; nt < NTN; nt++) {
                int nn = n0 + nt * 8 + gid;
                int c  = kk + tig * 2;
                uint32_t b0 = *reinterpret_cast<const uint32_t*>(&Ws[nn][c    ]);
                uint32_t b1 = *reinterpret_cast<const uint32_t*>(&Ws[nn][c + 8]);
                mma_f16(acc[0][nt], a[0], b0, b1);
                mma_f16(acc[1][nt], a[1], b0, b1);
            }
        }
    }
};

// FP16 GEMM: T = A @ W (A fp16 [n][K], Wt fp16 [BN][K]), fp16 output
template<int BN, int K>
__global__ void __launch_bounds__(256, 2)
gemm_f16_kernel(const __half* __restrict__ A, const __half* __restrict__ Wt,
                __half* __restrict__ T, int n)
{
    using C = HCore<BN, K>;
    constexpr int NTN = C::NTN;
    constexpr int NT  = K / 32;

    __shared__ __half As[2][128][HPAD];
    __shared__ __half Ws[2][BN][HPAD];

    const int tid  = threadIdx.x;
    const int wid  = tid >> 5, lane = tid & 31;
    const int m0   = (wid >> 1) * 32;
    const int n0   = (wid & 1) * (BN / 2);
    const int rowBase = blockIdx.x * 128;

    float acc[2][NTN][4];
    #pragma unroll
    for (int mt = 0; mt < 2; mt++)
        #pragma unroll
        for (int nt = 0; nt < NTN; nt++)
            #pragma unroll
            for (int q = 0; q < 4; q++) acc[mt][nt][q] = 0.0f;

    C::loadA(As[0], A, rowBase, 0, n, tid);
    C::loadW(Ws[0], Wt, 0, tid);
    cp_commit();

    #pragma unroll 1
    for (int t = 0; t < NT; t++) {
        int cur = t & 1, nxt = cur ^ 1;
        if (t + 1 < NT) {
            C::loadA(As[nxt], A, rowBase, (t + 1) * 32, n, tid);
            C::loadW(Ws[nxt], Wt, (t + 1) * 32, tid);
        }
        cp_commit();
        cp_wait<1>();
        __syncthreads();
        C::compute(As[cur], Ws[cur], acc, m0, n0, lane);
        __syncthreads();
    }

    const int gid = lane >> 2, tig = lane & 3;
    #pragma unroll
    for (int mt = 0; mt < 2; mt++) {
        #pragma unroll
        for (int nt = 0; nt < NTN; nt++) {
            int r = rowBase + m0 + mt * 16 + gid;
            int c = n0 + nt * 8 + tig * 2;
            if (r < n)
                *reinterpret_cast<__half2*>(T + (size_t)r * BN + c) =
                    __float22half2_rn(make_float2(acc[mt][nt][0], acc[mt][nt][1]));
            if (r + 8 < n)
                *reinterpret_cast<__half2*>(T + (size_t)(r + 8) * BN + c) =
                    __float22half2_rn(make_float2(acc[mt][nt][2], acc[mt][nt][3]));
        }
    }
}

// ---------------------------------------------------------------------------
// Gather aggregation: half-warp split, fp16 in, fp16 out.
// ---------------------------------------------------------------------------
__global__ void __launch_bounds__(256)
agg_gather_kernel(const int* __restrict__ ssrc, const int* __restrict__ offs,
                  const int* __restrict__ cnt, const float* __restrict__ dinv,
                  const float* __restrict__ bias, const __half* __restrict__ T,
                  __half* __restrict__ G, int n)
{
    int node = blockIdx.x * 8 + (threadIdx.x >> 5);
    if (node >= n) return;
    int lane = threadIdx.x & 31;
    int l16  = lane & 15;
    int h    = lane >> 4;

    float dv = dinv[node];
    float acc[8];
    if (h == 0) {
        uint4 u = *reinterpret_cast<const uint4*>(T + (size_t)node * HID + l16 * 8);
        const __half2* hp = reinterpret_cast<const __half2*>(&u);
        float4 b0 = *reinterpret_cast<const float4*>(bias + l16 * 8);
        float4 b1 = *reinterpret_cast<const float4*>(bias + l16 * 8 + 4);
        float d2 = dv * dv;
        float2 f0 = __half22float2(hp[0]), f1 = __half22float2(hp[1]);
        float2 f2 = __half22float2(hp[2]), f3 = __half22float2(hp[3]);
        acc[0] = d2 * f0.x + b0.x; acc[1] = d2 * f0.y + b0.y;
        acc[2] = d2 * f1.x + b0.z; acc[3] = d2 * f1.y + b0.w;
        acc[4] = d2 * f2.x + b1.x; acc[5] = d2 * f2.y + b1.y;
        acc[6] = d2 * f3.x + b1.z; acc[7] = d2 * f3.y + b1.w;
    } else {
        #pragma unroll
        for (int j = 0; j < 8; j++) acc[j] = 0.0f;
    }

    int beg = offs[node];
    int deg = cnt[node];
    int e = 0;
    for (; e + 7 < deg; e += 8) {
        int base = beg + e + h;
        int s0 = ssrc[base], s1 = ssrc[base + 2];
        int s2 = ssrc[base + 4], s3 = ssrc[base + 6];
        float n0 = dinv[s0] * dv, n1 = dinv[s1] * dv;
        float n2 = dinv[s2] * dv, n3 = dinv[s3] * dv;
        accum_row8(acc, T, s0, l16, n0);
        accum_row8(acc, T, s1, l16, n1);
        accum_row8(acc, T, s2, l16, n2);
        accum_row8(acc, T, s3, l16, n3);
    }
    for (; e + 1 < deg; e += 2) {
        int s0 = ssrc[beg + e + h];
        accum_row8(acc, T, s0, l16, dinv[s0] * dv);
    }
    if (e < deg && h == 0) {
        int s0 = ssrc[beg + e];
        accum_row8(acc, T, s0, l16, dinv[s0] * dv);
    }

    #pragma unroll
    for (int j = 0; j < 8; j++)
        acc[j] += __shfl_down_sync(0xFFFFFFFFu, acc[j], 16);

    if (h == 0) {
        uint4 u;
        __half2* hp = reinterpret_cast<__half2*>(&u);
        hp[0] = __float22half2_rn(make_float2(acc[0], acc[1]));
        hp[1] = __float22half2_rn(make_float2(acc[2], acc[3]));
        hp[2] = __float22half2_rn(make_float2(acc[4], acc[5]));
        hp[3] = __float22half2_rn(make_float2(acc[6], acc[7]));
        *reinterpret_cast<uint4*>(G + (size_t)node * HID + l16 * 8) = u;
    }
}

// ---------------------------------------------------------------------------
// Final layer FP16 GEMM + fused global max-pool (BN=64)
// ---------------------------------------------------------------------------
__device__ __forceinline__ void atomicMaxF(float* addr, float v) {
    if (v >= 0.0f) atomicMax((int*)addr, __float_as_int(v));
    else           atomicMin((unsigned int*)addr, __float_as_uint(v));
}

__global__ void __launch_bounds__(256, 2)
gemm_max_f16_kernel(const __half* __restrict__ A, const __half* __restrict__ Wt,
                    const float* __restrict__ bias, float* __restrict__ out, int n)
{
    constexpr int BN = OUTD;
    using C = HCore<BN, HID>;
    constexpr int NTN = C::NTN;
    constexpr int NT  = HID / 32;

    __shared__ __half As[2][128][HPAD];
    __shared__ __half Ws[2][BN][HPAD];
    __shared__ float red[OUTD];

    const int tid  = threadIdx.x;
    const int wid  = tid >> 5, lane = tid & 31;
    const int m0   = (wid >> 1) * 32;
    const int n0   = (wid & 1) * (BN / 2);
    const int rowBase = blockIdx.x * 128;

    if (tid < OUTD) red[tid] = __int_as_float(0xFF800000);

    float acc[2][NTN][4];
    #pragma unroll
    for (int mt = 0; mt < 2; mt++)
        #pragma unroll
        for (int nt = 0; nt < NTN; nt++)
            #pragma unroll
            for (int q = 0; q < 4; q++) acc[mt][nt][q] = 0.0f;

    C::loadA(As[0], A, rowBase, 0, n, tid);
    C::loadW(Ws[0], Wt, 0, tid);
    cp_commit();

    #pragma unroll 1
    for (int t = 0; t < NT; t++) {
        int cur = t & 1, nxt = cur ^ 1;
        if (t + 1 < NT) {
            C::loadA(As[nxt], A, rowBase, (t + 1) * 32, n, tid);
            C::loadW(Ws[nxt], Wt, (t + 1) * 32, tid);
        }
        cp_commit();
        cp_wait<1>();
        __syncthreads();
        C::compute(As[cur], Ws[cur], acc, m0, n0, lane);
        __syncthreads();
    }

    const int tig = lane & 3;
    #pragma unroll
    for (int nt = 0; nt < NTN; nt++) {
        int c = n0 + nt * 8 + tig * 2;
        float m0v = fmaxf(fmaxf(acc[0][nt][0], acc[0][nt][2]),
                          fmaxf(acc[1][nt][0], acc[1][nt][2]));
        float m1v = fmaxf(fmaxf(acc[0][nt][1], acc[0][nt][3]),
                          fmaxf(acc[1][nt][1], acc[1][nt][3]));
        atomicMaxF(&red[c],     m0v + bias[c]);
        atomicMaxF(&red[c + 1], m1v + bias[c + 1]);
    }
    __syncthreads();
    if (tid < OUTD) atomicMaxF(&out[tid], red[tid]);
}

// ---------------------------------------------------------------------------
// Launch
// ---------------------------------------------------------------------------
extern "C" void kernel_launch(void* const* d_in, const int* in_sizes, int n_in,
                              void* d_out, int out_size)
{
    const float* x    = (const float*)d_in[0];
    const int*   ei   = (const int*)  d_in[1];
    const float* W0   = (const float*)d_in[3];
    const float* b0   = (const float*)d_in[4];
    const float* W1   = (const float*)d_in[5];
    const float* b1   = (const float*)d_in[6];
    const float* W2   = (const float*)d_in[7];
    const float* b2   = (const float*)d_in[8];
    const float* Wlin = (const float*)d_in[9];
    const float* blin = (const float*)d_in[10];
    float* out = (float*)d_out;

    const int n = in_sizes[0] / FIN;
    const int E = in_sizes[1] / 2;

    __half *pXh, *pT, *pG1, *pG2, *pW0t, *pW1t, *pW2t, *pWlt;
    float *pD;
    int *pCnt, *pOffs, *pFlags, *pAggv, *pPrefv, *pSrc, *pRank;
    cudaGetSymbolAddress((void**)&pXh, g_xh);
    cudaGetSymbolAddress((void**)&pT, g_T);
    cudaGetSymbolAddress((void**)&pG1, g_G1);
    cudaGetSymbolAddress((void**)&pG2, g_G2);
    cudaGetSymbolAddress((void**)&pW0t, g_W0t);
    cudaGetSymbolAddress((void**)&pW1t, g_W1t);
    cudaGetSymbolAddress((void**)&pW2t, g_W2t);
    cudaGetSymbolAddress((void**)&pWlt, g_Wlt);
    cudaGetSymbolAddress((void**)&pD, g_dinv);
    cudaGetSymbolAddress((void**)&pCnt, g_cnt);
    cudaGetSymbolAddress((void**)&pOffs, g_offs);
    cudaGetSymbolAddress((void**)&pFlags, g_flags);
    cudaGetSymbolAddress((void**)&pAggv, g_aggv);
    cudaGetSymbolAddress((void**)&pPrefv, g_prefv);
    cudaGetSymbolAddress((void**)&pSrc, g_ssrc);
    cudaGetSymbolAddress((void**)&pRank, g_rank);

    const int prepBlocks = (n * FIN / 8 + 255) / 256;
    const int edgeBlocks = (E + 255) / 256;
    const int gemmBlocks = (n + 127) / 128;
    const int scanBlocks = (n + SCAN_B - 1) / SCAN_B;
    const int aggBlocks  = (n + 7) / 8;

    // prep: zero cnt/flags, out init, x->fp16, weight converts
    prep_kernel<<<prepBlocks, 256>>>(x, W0, W1, W2, Wlin, pXh, pW0t, pW1t,
                                     pW2t, pWlt, pCnt, pFlags, out, n);

    // CSR build
    hist_kernel<<<edgeBlocks, 256>>>(ei, pCnt, pRank, E);
    scan_fused_kernel<<<scanBlocks, SCAN_B>>>(pCnt, pOffs, pD, pFlags,
                                              pAggv, pPrefv, n);
    scatter_edges_kernel<<<edgeBlocks, 256>>>(ei, pOffs, pRank, pSrc, E);

    // layer 0 (fp16, K=256)
    gemm_f16_kernel<HID, FIN><<<gemmBlocks, 256>>>(pXh, pW0t, pT, n);
    agg_gather_kernel<<<aggBlocks, 256>>>(pSrc, pOffs, pCnt, pD, b0, pT, pG1, n);
    // layer 1 (fp16)
    gemm_f16_kernel<HID, HID><<<gemmBlocks, 256>>>(pG1, pW1t, pT, n);
    agg_gather_kernel<<<aggBlocks, 256>>>(pSrc, pOffs, pCnt, pD, b1, pT, pG2, n);
    // layer 2 (fp16)
    gemm_f16_kernel<HID, HID><<<gemmBlocks, 256>>>(pG2, pW2t, pT, n);
    agg_gather_kernel<<<aggBlocks, 256>>>(pSrc, pOffs, pCnt, pD, b2, pT, pG1, n);

    // final (fp16 + max-pool)
    gemm_max_f16_kernel<<<gemmBlocks, 256>>>(pG1, pWlt, blin, out, n);
}

// round 12
// speedup vs baseline: 1.0400x; 1.0400x over previous
#include <cuda_runtime.h>
#include <cuda_fp16.h>
#include <cstdint>
#include <cstddef>

#define FIN   256
#define HID   128
#define OUTD  64
#define MAXN  50176
#define MAXE  800000
#define SCAN_B 256

__device__ __align__(16) __half g_T[(size_t)MAXN * HID];   // post-GEMM features
__device__ __align__(16) __half g_G1[(size_t)MAXN * HID];  // aggregated (fp16)
__device__ __align__(16) __half g_G2[(size_t)MAXN * HID];
__device__ __align__(16) __half g_W1t[HID * HID];          // transposed fp16 weights
__device__ __align__(16) __half g_W2t[HID * HID];
__device__ __align__(16) __half g_Wlt[OUTD * HID];
__device__ float  g_dinv[MAXN];
__device__ int    g_cnt[MAXN];
__device__ int    g_offs[MAXN];
__device__ int    g_bsum[SCAN_B];
__device__ int    g_bbase[SCAN_B];
__device__ __align__(16) int g_ssrc[MAXE];
__device__ __align__(16) int g_rank[MAXE];

// ---------------------------------------------------------------------------
// PTX helpers
// ---------------------------------------------------------------------------
__device__ __forceinline__ void cp_async16(void* smem_dst, const void* gmem_src) {
    uint32_t s = (uint32_t)__cvta_generic_to_shared(smem_dst);
    asm volatile("cp.async.cg.shared.global [%0], [%1], 16;\n" :: "r"(s), "l"(gmem_src));
}
__device__ __forceinline__ void cp_commit() {
    asm volatile("cp.async.commit_group;\n");
}
template<int N>
__device__ __forceinline__ void cp_wait() {
    asm volatile("cp.async.wait_group %0;\n" :: "n"(N));
}
__device__ __forceinline__ uint32_t f2tf(float f) {
    uint32_t r;
    asm("cvt.rna.tf32.f32 %0, %1;" : "=r"(r) : "f"(f));
    return r;
}
__device__ __forceinline__ void mma_tf32(float c[4], const uint32_t a[4],
                                         uint32_t b0, uint32_t b1) {
    asm volatile(
        "mma.sync.aligned.m16n8k8.row.col.f32.tf32.tf32.f32 "
        "{%0,%1,%2,%3}, {%4,%5,%6,%7}, {%8,%9}, {%0,%1,%2,%3};"
        : "+f"(c[0]), "+f"(c[1]), "+f"(c[2]), "+f"(c[3])
        : "r"(a[0]), "r"(a[1]), "r"(a[2]), "r"(a[3]), "r"(b0), "r"(b1));
}
__device__ __forceinline__ void mma_f16(float c[4], const uint32_t a[4],
                                        uint32_t b0, uint32_t b1) {
    asm volatile(
        "mma.sync.aligned.m16n8k16.row.col.f32.f16.f16.f32 "
        "{%0,%1,%2,%3}, {%4,%5,%6,%7}, {%8,%9}, {%0,%1,%2,%3};"
        : "+f"(c[0]), "+f"(c[1]), "+f"(c[2]), "+f"(c[3])
        : "r"(a[0]), "r"(a[1]), "r"(a[2]), "r"(a[3]), "r"(b0), "r"(b1));
}
// accumulate 8 halfs (one uint4) scaled by nr into acc[8]
__device__ __forceinline__ void accum_row8(float acc[8], const __half* __restrict__ T,
                                           int row, int l16, float nr) {
    uint4 u = *reinterpret_cast<const uint4*>(T + (size_t)row * HID + l16 * 8);
    const __half2* hp = reinterpret_cast<const __half2*>(&u);
    #pragma unroll
    for (int q = 0; q < 4; q++) {
        float2 f = __half22float2(hp[q]);
        acc[2*q]   += nr * f.x;
        acc[2*q+1] += nr * f.y;
    }
}

// ---------------------------------------------------------------------------
// Weight conversion: fp32 [k][n] -> fp16 transposed [n][k]
// ---------------------------------------------------------------------------
__global__ void convert_w_kernel(const float* __restrict__ W1,
                                 const float* __restrict__ W2,
                                 const float* __restrict__ Wl,
                                 __half* __restrict__ W1t,
                                 __half* __restrict__ W2t,
                                 __half* __restrict__ Wlt) {
    int t = blockIdx.x * blockDim.x + threadIdx.x;
    if (t < HID * HID) {
        int k = t / HID, n2 = t % HID;
        W1t[n2 * HID + k] = __float2half(W1[t]);
        W2t[n2 * HID + k] = __float2half(W2[t]);
    }
    if (t < HID * OUTD) {
        int k = t / OUTD, n2 = t % OUTD;
        Wlt[n2 * HID + k] = __float2half(Wl[t]);
    }
}

// ---------------------------------------------------------------------------
// CSR build: histogram(+rank) -> block scan -> rank-scatter
// 4 edges per thread (int4) for MLP in the latency-bound random phases.
// ---------------------------------------------------------------------------
__global__ void zero_cnt_kernel(int* cnt, int n) {
    int i = blockIdx.x * blockDim.x + threadIdx.x;
    if (i < n) cnt[i] = 0;
}
__global__ void hist_kernel(const int* __restrict__ ei, int* cnt, int* rank, int E) {
    int e = (blockIdx.x * blockDim.x + threadIdx.x) * 4;
    if (e + 3 < E) {
        int4 d = *reinterpret_cast<const int4*>(ei + E + e);
        int4 r;
        r.x = atomicAdd(&cnt[d.x], 1);
        r.y = atomicAdd(&cnt[d.y], 1);
        r.z = atomicAdd(&cnt[d.z], 1);
        r.w = atomicAdd(&cnt[d.w], 1);
        *reinterpret_cast<int4*>(rank + e) = r;
    } else {
        for (; e < E; e++) rank[e] = atomicAdd(&cnt[ei[E + e]], 1);
    }
}
__global__ void scan_block_kernel(const int* __restrict__ cnt, int* offs,
                                  int* bsum, int n) {
    __shared__ int sm[SCAN_B];
    int i = blockIdx.x * SCAN_B + threadIdx.x;
    int v = (i < n) ? cnt[i] : 0;
    sm[threadIdx.x] = v;
    __syncthreads();
    #pragma unroll
    for (int o = 1; o < SCAN_B; o <<= 1) {
        int y = (threadIdx.x >= o) ? sm[threadIdx.x - o] : 0;
        __syncthreads();
        sm[threadIdx.x] += y;
        __syncthreads();
    }
    if (i < n) offs[i] = sm[threadIdx.x] - v;
    if (threadIdx.x == SCAN_B - 1) bsum[blockIdx.x] = sm[SCAN_B - 1];
}
__global__ void scan_top_kernel(const int* __restrict__ bsum, int* bbase, int nb) {
    __shared__ int sm[SCAN_B];
    int v = (threadIdx.x < nb) ? bsum[threadIdx.x] : 0;
    sm[threadIdx.x] = v;
    __syncthreads();
    #pragma unroll
    for (int o = 1; o < SCAN_B; o <<= 1) {
        int y = (threadIdx.x >= o) ? sm[threadIdx.x - o] : 0;
        __syncthreads();
        sm[threadIdx.x] += y;
        __syncthreads();
    }
    if (threadIdx.x < nb) bbase[threadIdx.x] = sm[threadIdx.x] - v;
}
__global__ void finalize_offs_kernel(int* offs, const int* __restrict__ bbase,
                                     const int* __restrict__ cnt,
                                     float* dinv, int n) {
    int i = blockIdx.x * blockDim.x + threadIdx.x;
    if (i < n) {
        offs[i] += bbase[i / SCAN_B];
        dinv[i] = rsqrtf((float)(cnt[i] + 1));
    }
}
__global__ void scatter_edges_kernel(const int* __restrict__ ei,
                                     const int* __restrict__ offs,
                                     const int* __restrict__ rank,
                                     int* ssrc, int E) {
    int e = (blockIdx.x * blockDim.x + threadIdx.x) * 4;
    if (e + 3 < E) {
        int4 s = *reinterpret_cast<const int4*>(ei + e);
        int4 d = *reinterpret_cast<const int4*>(ei + E + e);
        int4 r = *reinterpret_cast<const int4*>(rank + e);
        int o0 = offs[d.x], o1 = offs[d.y], o2 = offs[d.z], o3 = offs[d.w];
        ssrc[o0 + r.x] = s.x;
        ssrc[o1 + r.y] = s.y;
        ssrc[o2 + r.z] = s.z;
        ssrc[o3 + r.w] = s.w;
    } else {
        for (; e < E; e++)
            ssrc[offs[ei[E + e]] + rank[e]] = ei[e];
    }
}

// ---------------------------------------------------------------------------
// TF32 tensor-core GEMM core (layer 0: fp32 A input)
// ---------------------------------------------------------------------------
#define APAD 20

template<int K, int BN>
struct TCore {
    static constexpr int WPAD = BN + 8;
    static constexpr int NTN  = (BN / 2) / 8;

    static __device__ __forceinline__
    void loadA(float (*As)[APAD], const float* __restrict__ A,
               int rowBase, int kt, int n, int tid) {
        #pragma unroll
        for (int i = 0; i < 2; i++) {
            int ch  = i * 256 + tid;
            int row = ch >> 2;
            int cin = (ch & 3) * 4;
            int grow = rowBase + row;
            if (grow >= n) grow = n - 1;
            cp_async16(&As[row][cin], A + (size_t)grow * K + kt + cin);
        }
    }
    static __device__ __forceinline__
    void loadW(float (*Ws)[WPAD], const float* __restrict__ W, int kt, int tid) {
        constexpr int CPK = BN / 4;
        constexpr int NCH = 16 * CPK;
        #pragma unroll
        for (int i = 0; i < NCH / 256; i++) {
            int ch  = i * 256 + tid;
            int k   = ch / CPK;
            int cin = (ch % CPK) * 4;
            cp_async16(&Ws[k][cin], W + (size_t)(kt + k) * BN + cin);
        }
    }
    static __device__ __forceinline__
    void compute(const float (*As)[APAD], const float (*Ws)[WPAD],
                 float acc[2][NTN][4], int m0, int n0, int lane) {
        const int gid = lane >> 2;
        const int tig = lane & 3;
        #pragma unroll
        for (int kk = 0; kk < 16; kk += 8) {
            uint32_t a[2][4];
            #pragma unroll
            for (int mt = 0; mt < 2; mt++) {
                int r = m0 + mt * 16 + gid;
                int c = kk + tig;
                a[mt][0] = f2tf(As[r    ][c    ]);
                a[mt][1] = f2tf(As[r + 8][c    ]);
                a[mt][2] = f2tf(As[r    ][c + 4]);
                a[mt][3] = f2tf(As[r + 8][c + 4]);
            }
            #pragma unroll
            for (int nt = 0; nt < NTN; nt++) {
                int c  = n0 + nt * 8 + gid;
                int kb = kk + tig;
                uint32_t b0 = f2tf(Ws[kb    ][c]);
                uint32_t b1 = f2tf(Ws[kb + 4][c]);
                mma_tf32(acc[0][nt], a[0], b0, b1);
                mma_tf32(acc[1][nt], a[1], b0, b1);
            }
        }
    }
};

// ---------------------------------------------------------------------------
// Layer-0 TF32 GEMM: T = x @ W0, fp16 output
// ---------------------------------------------------------------------------
template<int K, int BN>
__global__ void __launch_bounds__(256, 2)
gemm_tf32_kernel(const float* __restrict__ A, const float* __restrict__ W,
                 __half* __restrict__ T, int n)
{
    using C = TCore<K, BN>;
    constexpr int NTN = C::NTN;
    constexpr int NT  = K / 16;

    __shared__ float As[2][128][APAD];
    __shared__ float Ws[2][16][C::WPAD];

    const int tid  = threadIdx.x;
    const int wid  = tid >> 5, lane = tid & 31;
    const int m0   = (wid >> 1) * 32;
    const int n0   = (wid & 1) * (BN / 2);
    const int rowBase = blockIdx.x * 128;

    float acc[2][NTN][4];
    #pragma unroll
    for (int mt = 0; mt < 2; mt++)
        #pragma unroll
        for (int nt = 0; nt < NTN; nt++)
            #pragma unroll
            for (int q = 0; q < 4; q++) acc[mt][nt][q] = 0.0f;

    C::loadA(As[0], A, rowBase, 0, n, tid);
    C::loadW(Ws[0], W, 0, tid);
    cp_commit();

    #pragma unroll 1
    for (int t = 0; t < NT; t++) {
        int cur = t & 1, nxt = cur ^ 1;
        if (t + 1 < NT) {
            C::loadA(As[nxt], A, rowBase, (t + 1) * 16, n, tid);
            C::loadW(Ws[nxt], W, (t + 1) * 16, tid);
        }
        cp_commit();
        cp_wait<1>();
        __syncthreads();
        C::compute(As[cur], Ws[cur], acc, m0, n0, lane);
        __syncthreads();
    }

    const int gid = lane >> 2, tig = lane & 3;
    #pragma unroll
    for (int mt = 0; mt < 2; mt++) {
        #pragma unroll
        for (int nt = 0; nt < NTN; nt++) {
            int r = rowBase + m0 + mt * 16 + gid;
            int c = n0 + nt * 8 + tig * 2;
            if (r < n)
                *reinterpret_cast<__half2*>(T + (size_t)r * BN + c) =
                    __float22half2_rn(make_float2(acc[mt][nt][0], acc[mt][nt][1]));
            if (r + 8 < n)
                *reinterpret_cast<__half2*>(T + (size_t)(r + 8) * BN + c) =
                    __float22half2_rn(make_float2(acc[mt][nt][2], acc[mt][nt][3]));
        }
    }
}

// ---------------------------------------------------------------------------
// FP16 tensor-core GEMM core. K=128, BK=32 halfs, fp16 A + transposed fp16 W.
// ---------------------------------------------------------------------------
#define HPAD 40

template<int BN>
struct HCore {
    static constexpr int K   = HID;
    static constexpr int NTN = (BN / 2) / 8;

    static __device__ __forceinline__
    void loadA(__half (*As)[HPAD], const __half* __restrict__ A,
               int rowBase, int kt, int n, int tid) {
        #pragma unroll
        for (int i = 0; i < 2; i++) {
            int ch  = i * 256 + tid;
            int row = ch >> 2;
            int cin = (ch & 3) * 8;
            int grow = rowBase + row;
            if (grow >= n) grow = n - 1;
            cp_async16(&As[row][cin], A + (size_t)grow * K + kt + cin);
        }
    }
    static __device__ __forceinline__
    void loadW(__half (*Ws)[HPAD], const __half* __restrict__ Wt, int kt, int tid) {
        constexpr int NCH = BN * 4;
        #pragma unroll
        for (int i = 0; i < NCH / 256; i++) {
            int ch  = i * 256 + tid;
            int nn  = ch >> 2;
            int cin = (ch & 3) * 8;
            cp_async16(&Ws[nn][cin], Wt + (size_t)nn * K + kt + cin);
        }
    }
    static __device__ __forceinline__
    void compute(const __half (*As)[HPAD], const __half (*Ws)[HPAD],
                 float acc[2][NTN][4], int m0, int n0, int lane) {
        const int gid = lane >> 2;
        const int tig = lane & 3;
        #pragma unroll
        for (int kk = 0; kk < 32; kk += 16) {
            uint32_t a[2][4];
            #pragma unroll
            for (int mt = 0; mt < 2; mt++) {
                int r = m0 + mt * 16 + gid;
                int c = kk + tig * 2;
                a[mt][0] = *reinterpret_cast<const uint32_t*>(&As[r    ][c    ]);
                a[mt][1] = *reinterpret_cast<const uint32_t*>(&As[r + 8][c    ]);
                a[mt][2] = *reinterpret_cast<const uint32_t*>(&As[r    ][c + 8]);
                a[mt][3] = *reinterpret_cast<const uint32_t*>(&As[r + 8][c + 8]);
            }
            #pragma unroll
            for (int nt = 0; nt < NTN; nt++) {
                int nn = n0 + nt * 8 + gid;
                int c  = kk + tig * 2;
                uint32_t b0 = *reinterpret_cast<const uint32_t*>(&Ws[nn][c    ]);
                uint32_t b1 = *reinterpret_cast<const uint32_t*>(&Ws[nn][c + 8]);
                mma_f16(acc[0][nt], a[0], b0, b1);
                mma_f16(acc[1][nt], a[1], b0, b1);
            }
        }
    }
};

// FP16 GEMM: T = A @ W (A fp16, Wt fp16 transposed), fp16 output
template<int BN>
__global__ void __launch_bounds__(256, 2)
gemm_f16_kernel(const __half* __restrict__ A, const __half* __restrict__ Wt,
                __half* __restrict__ T, int n)
{
    using C = HCore<BN>;
    constexpr int NTN = C::NTN;
    constexpr int NT  = HID / 32;

    __shared__ __half As[2][128][HPAD];
    __shared__ __half Ws[2][BN][HPAD];

    const int tid  = threadIdx.x;
    const int wid  = tid >> 5, lane = tid & 31;
    const int m0   = (wid >> 1) * 32;
    const int n0   = (wid & 1) * (BN / 2);
    const int rowBase = blockIdx.x * 128;

    float acc[2][NTN][4];
    #pragma unroll
    for (int mt = 0; mt < 2; mt++)
        #pragma unroll
        for (int nt = 0; nt < NTN; nt++)
            #pragma unroll
            for (int q = 0; q < 4; q++) acc[mt][nt][q] = 0.0f;

    C::loadA(As[0], A, rowBase, 0, n, tid);
    C::loadW(Ws[0], Wt, 0, tid);
    cp_commit();

    #pragma unroll 1
    for (int t = 0; t < NT; t++) {
        int cur = t & 1, nxt = cur ^ 1;
        if (t + 1 < NT) {
            C::loadA(As[nxt], A, rowBase, (t + 1) * 32, n, tid);
            C::loadW(Ws[nxt], Wt, (t + 1) * 32, tid);
        }
        cp_commit();
        cp_wait<1>();
        __syncthreads();
        C::compute(As[cur], Ws[cur], acc, m0, n0, lane);
        __syncthreads();
    }

    const int gid = lane >> 2, tig = lane & 3;
    #pragma unroll
    for (int mt = 0; mt < 2; mt++) {
        #pragma unroll
        for (int nt = 0; nt < NTN; nt++) {
            int r = rowBase + m0 + mt * 16 + gid;
            int c = n0 + nt * 8 + tig * 2;
            if (r < n)
                *reinterpret_cast<__half2*>(T + (size_t)r * BN + c) =
                    __float22half2_rn(make_float2(acc[mt][nt][0], acc[mt][nt][1]));
            if (r + 8 < n)
                *reinterpret_cast<__half2*>(T + (size_t)(r + 8) * BN + c) =
                    __float22half2_rn(make_float2(acc[mt][nt][2], acc[mt][nt][3]));
        }
    }
}

// ---------------------------------------------------------------------------
// Gather aggregation: half-warp split, fp16 in, fp16 out.
// ---------------------------------------------------------------------------
__global__ void __launch_bounds__(256)
agg_gather_kernel(const int* __restrict__ ssrc, const int* __restrict__ offs,
                  const int* __restrict__ cnt, const float* __restrict__ dinv,
                  const float* __restrict__ bias, const __half* __restrict__ T,
                  __half* __restrict__ G, int n)
{
    int node = blockIdx.x * 8 + (threadIdx.x >> 5);
    if (node >= n) return;
    int lane = threadIdx.x & 31;
    int l16  = lane & 15;
    int h    = lane >> 4;

    float dv = dinv[node];
    float acc[8];
    if (h == 0) {
        uint4 u = *reinterpret_cast<const uint4*>(T + (size_t)node * HID + l16 * 8);
        const __half2* hp = reinterpret_cast<const __half2*>(&u);
        float4 b0 = *reinterpret_cast<const float4*>(bias + l16 * 8);
        float4 b1 = *reinterpret_cast<const float4*>(bias + l16 * 8 + 4);
        float d2 = dv * dv;
        float2 f0 = __half22float2(hp[0]), f1 = __half22float2(hp[1]);
        float2 f2 = __half22float2(hp[2]), f3 = __half22float2(hp[3]);
        acc[0] = d2 * f0.x + b0.x; acc[1] = d2 * f0.y + b0.y;
        acc[2] = d2 * f1.x + b0.z; acc[3] = d2 * f1.y + b0.w;
        acc[4] = d2 * f2.x + b1.x; acc[5] = d2 * f2.y + b1.y;
        acc[6] = d2 * f3.x + b1.z; acc[7] = d2 * f3.y + b1.w;
    } else {
        #pragma unroll
        for (int j = 0; j < 8; j++) acc[j] = 0.0f;
    }

    int beg = offs[node];
    int deg = cnt[node];
    int e = 0;
    for (; e + 7 < deg; e += 8) {
        int base = beg + e + h;
        int s0 = ssrc[base], s1 = ssrc[base + 2];
        int s2 = ssrc[base + 4], s3 = ssrc[base + 6];
        float n0 = dinv[s0] * dv, n1 = dinv[s1] * dv;
        float n2 = dinv[s2] * dv, n3 = dinv[s3] * dv;
        accum_row8(acc, T, s0, l16, n0);
        accum_row8(acc, T, s1, l16, n1);
        accum_row8(acc, T, s2, l16, n2);
        accum_row8(acc, T, s3, l16, n3);
    }
    for (; e + 1 < deg; e += 2) {
        int s0 = ssrc[beg + e + h];
        accum_row8(acc, T, s0, l16, dinv[s0] * dv);
    }
    if (e < deg && h == 0) {
        int s0 = ssrc[beg + e];
        accum_row8(acc, T, s0, l16, dinv[s0] * dv);
    }

    #pragma unroll
    for (int j = 0; j < 8; j++)
        acc[j] += __shfl_down_sync(0xFFFFFFFFu, acc[j], 16);

    if (h == 0) {
        uint4 u;
        __half2* hp = reinterpret_cast<__half2*>(&u);
        hp[0] = __float22half2_rn(make_float2(acc[0], acc[1]));
        hp[1] = __float22half2_rn(make_float2(acc[2], acc[3]));
        hp[2] = __float22half2_rn(make_float2(acc[4], acc[5]));
        hp[3] = __float22half2_rn(make_float2(acc[6], acc[7]));
        *reinterpret_cast<uint4*>(G + (size_t)node * HID + l16 * 8) = u;
    }
}

// ---------------------------------------------------------------------------
// Final layer FP16 GEMM + fused global max-pool (BN=64)
// ---------------------------------------------------------------------------
__device__ __forceinline__ void atomicMaxF(float* addr, float v) {
    if (v >= 0.0f) atomicMax((int*)addr, __float_as_int(v));
    else           atomicMin((unsigned int*)addr, __float_as_uint(v));
}

__global__ void init_out_kernel(float* out) {
    if (threadIdx.x < OUTD) out[threadIdx.x] = __int_as_float(0xFF800000);
}

__global__ void __launch_bounds__(256, 2)
gemm_max_f16_kernel(const __half* __restrict__ A, const __half* __restrict__ Wt,
                    const float* __restrict__ bias, float* __restrict__ out, int n)
{
    constexpr int BN = OUTD;
    using C = HCore<BN>;
    constexpr int NTN = C::NTN;
    constexpr int NT  = HID / 32;

    __shared__ __half As[2][128][HPAD];
    __shared__ __half Ws[2][BN][HPAD];
    __shared__ float red[OUTD];

    const int tid  = threadIdx.x;
    const int wid  = tid >> 5, lane = tid & 31;
    const int m0   = (wid >> 1) * 32;
    const int n0   = (wid & 1) * (BN / 2);
    const int rowBase = blockIdx.x * 128;

    if (tid < OUTD) red[tid] = __int_as_float(0xFF800000);

    float acc[2][NTN][4];
    #pragma unroll
    for (int mt = 0; mt < 2; mt++)
        #pragma unroll
        for (int nt = 0; nt < NTN; nt++)
            #pragma unroll
            for (int q = 0; q < 4; q++) acc[mt][nt][q] = 0.0f;

    C::loadA(As[0], A, rowBase, 0, n, tid);
    C::loadW(Ws[0], Wt, 0, tid);
    cp_commit();

    #pragma unroll 1
    for (int t = 0; t < NT; t++) {
        int cur = t & 1, nxt = cur ^ 1;
        if (t + 1 < NT) {
            C::loadA(As[nxt], A, rowBase, (t + 1) * 32, n, tid);
            C::loadW(Ws[nxt], Wt, (t + 1) * 32, tid);
        }
        cp_commit();
        cp_wait<1>();
        __syncthreads();
        C::compute(As[cur], Ws[cur], acc, m0, n0, lane);
        __syncthreads();
    }

    const int tig = lane & 3;
    #pragma unroll
    for (int nt = 0; nt < NTN; nt++) {
        int c = n0 + nt * 8 + tig * 2;
        float m0v = fmaxf(fmaxf(acc[0][nt][0], acc[0][nt][2]),
                          fmaxf(acc[1][nt][0], acc[1][nt][2]));
        float m1v = fmaxf(fmaxf(acc[0][nt][1], acc[0][nt][3]),
                          fmaxf(acc[1][nt][1], acc[1][nt][3]));
        atomicMaxF(&red[c],     m0v + bias[c]);
        atomicMaxF(&red[c + 1], m1v + bias[c + 1]);
    }
    __syncthreads();
    if (tid < OUTD) atomicMaxF(&out[tid], red[tid]);
}

// ---------------------------------------------------------------------------
// Launch
// ---------------------------------------------------------------------------
extern "C" void kernel_launch(void* const* d_in, const int* in_sizes, int n_in,
                              void* d_out, int out_size)
{
    const float* x    = (const float*)d_in[0];
    const int*   ei   = (const int*)  d_in[1];
    const float* W0   = (const float*)d_in[3];
    const float* b0   = (const float*)d_in[4];
    const float* W1   = (const float*)d_in[5];
    const float* b1   = (const float*)d_in[6];
    const float* W2   = (const float*)d_in[7];
    const float* b2   = (const float*)d_in[8];
    const float* Wlin = (const float*)d_in[9];
    const float* blin = (const float*)d_in[10];
    float* out = (float*)d_out;

    const int n = in_sizes[0] / FIN;
    const int E = in_sizes[1] / 2;

    __half *pT, *pG1, *pG2, *pW1t, *pW2t, *pWlt;
    float *pD;
    int *pCnt, *pOffs, *pBs, *pBb, *pSrc, *pRank;
    cudaGetSymbolAddress((void**)&pT, g_T);
    cudaGetSymbolAddress((void**)&pG1, g_G1);
    cudaGetSymbolAddress((void**)&pG2, g_G2);
    cudaGetSymbolAddress((void**)&pW1t, g_W1t);
    cudaGetSymbolAddress((void**)&pW2t, g_W2t);
    cudaGetSymbolAddress((void**)&pWlt, g_Wlt);
    cudaGetSymbolAddress((void**)&pD, g_dinv);
    cudaGetSymbolAddress((void**)&pCnt, g_cnt);
    cudaGetSymbolAddress((void**)&pOffs, g_offs);
    cudaGetSymbolAddress((void**)&pBs, g_bsum);
    cudaGetSymbolAddress((void**)&pBb, g_bbase);
    cudaGetSymbolAddress((void**)&pSrc, g_ssrc);
    cudaGetSymbolAddress((void**)&pRank, g_rank);

    const int nodeBlocks = (n + 255) / 256;
    const int edge4Blocks = (E / 4 + 255) / 256;
    const int gemmBlocks = (n + 127) / 128;
    const int scanBlocks = (n + SCAN_B - 1) / SCAN_B;
    const int aggBlocks  = (n + 7) / 8;

    // weight conversion (independent; before layer 1)
    convert_w_kernel<<<(HID * HID + 255) / 256, 256>>>(W1, W2, Wlin, pW1t, pW2t, pWlt);

    // CSR build + normalization
    zero_cnt_kernel<<<nodeBlocks, 256>>>(pCnt, n);
    hist_kernel<<<edge4Blocks, 256>>>(ei, pCnt, pRank, E);
    scan_block_kernel<<<scanBlocks, SCAN_B>>>(pCnt, pOffs, pBs, n);
    scan_top_kernel<<<1, SCAN_B>>>(pBs, pBb, scanBlocks);
    finalize_offs_kernel<<<nodeBlocks, 256>>>(pOffs, pBb, pCnt, pD, n);
    scatter_edges_kernel<<<edge4Blocks, 256>>>(ei, pOffs, pRank, pSrc, E);

    // layer 0 (tf32 from fp32 x)
    gemm_tf32_kernel<FIN, HID><<<gemmBlocks, 256>>>(x, W0, pT, n);
    agg_gather_kernel<<<aggBlocks, 256>>>(pSrc, pOffs, pCnt, pD, b0, pT, pG1, n);
    // layer 1 (fp16)
    gemm_f16_kernel<HID><<<gemmBlocks, 256>>>(pG1, pW1t, pT, n);
    agg_gather_kernel<<<aggBlocks, 256>>>(pSrc, pOffs, pCnt, pD, b1, pT, pG2, n);
    // layer 2 (fp16)
    gemm_f16_kernel<HID><<<gemmBlocks, 256>>>(pG2, pW2t, pT, n);
    agg_gather_kernel<<<aggBlocks, 256>>>(pSrc, pOffs, pCnt, pD, b2, pT, pG1, n);

    // final (fp16 + max-pool)
    init_out_kernel<<<1, 64>>>(out);
    gemm_max_f16_kernel<<<gemmBlocks, 256>>>(pG1, pWlt, blin, out, n);
}

// round 13
// speedup vs baseline: 1.1032x; 1.0607x over previous
#include <cuda_runtime.h>
#include <cuda_fp16.h>
#include <cstdint>
#include <cstddef>

#define FIN   256
#define HID   128
#define OUTD  64
#define MAXN  50176
#define MAXE  800000
#define SCAN_B 256

__device__ __align__(16) __half g_T[(size_t)MAXN * HID];   // post-GEMM features
__device__ __align__(16) __half g_G1[(size_t)MAXN * HID];  // aggregated (fp16)
__device__ __align__(16) __half g_G2[(size_t)MAXN * HID];
__device__ __align__(16) __half g_W0t[HID * FIN];          // transposed fp16 weights
__device__ __align__(16) __half g_W1t[HID * HID];
__device__ __align__(16) __half g_W2t[HID * HID];
__device__ __align__(16) __half g_Wlt[OUTD * HID];
__device__ float  g_dinv[MAXN];
__device__ int    g_cnt[MAXN];
__device__ int    g_offs[MAXN];
__device__ int    g_bsum[SCAN_B];
__device__ int    g_bbase[SCAN_B];
__device__ __align__(16) int g_ssrc[MAXE];
__device__ __align__(16) int g_rank[MAXE];

// ---------------------------------------------------------------------------
// PTX helpers
// ---------------------------------------------------------------------------
__device__ __forceinline__ void cp_async16(void* smem_dst, const void* gmem_src) {
    uint32_t s = (uint32_t)__cvta_generic_to_shared(smem_dst);
    asm volatile("cp.async.cg.shared.global [%0], [%1], 16;\n" :: "r"(s), "l"(gmem_src));
}
__device__ __forceinline__ void cp_commit() {
    asm volatile("cp.async.commit_group;\n");
}
template<int N>
__device__ __forceinline__ void cp_wait() {
    asm volatile("cp.async.wait_group %0;\n" :: "n"(N));
}
__device__ __forceinline__ void mma_f16(float c[4], const uint32_t a[4],
                                        uint32_t b0, uint32_t b1) {
    asm volatile(
        "mma.sync.aligned.m16n8k16.row.col.f32.f16.f16.f32 "
        "{%0,%1,%2,%3}, {%4,%5,%6,%7}, {%8,%9}, {%0,%1,%2,%3};"
        : "+f"(c[0]), "+f"(c[1]), "+f"(c[2]), "+f"(c[3])
        : "r"(a[0]), "r"(a[1]), "r"(a[2]), "r"(a[3]), "r"(b0), "r"(b1));
}
// accumulate 8 halfs (one uint4) scaled by nr into acc[8]
__device__ __forceinline__ void accum_row8(float acc[8], const __half* __restrict__ T,
                                           int row, int l16, float nr) {
    uint4 u = *reinterpret_cast<const uint4*>(T + (size_t)row * HID + l16 * 8);
    const __half2* hp = reinterpret_cast<const __half2*>(&u);
    #pragma unroll
    for (int q = 0; q < 4; q++) {
        float2 f = __half22float2(hp[q]);
        acc[2*q]   += nr * f.x;
        acc[2*q+1] += nr * f.y;
    }
}

// ---------------------------------------------------------------------------
// Weight conversion: fp32 [k][n] -> fp16 transposed [n][k] (incl. W0)
// ---------------------------------------------------------------------------
__global__ void convert_w_kernel(const float* __restrict__ W0,
                                 const float* __restrict__ W1,
                                 const float* __restrict__ W2,
                                 const float* __restrict__ Wl,
                                 __half* __restrict__ W0t,
                                 __half* __restrict__ W1t,
                                 __half* __restrict__ W2t,
                                 __half* __restrict__ Wlt) {
    int t = blockIdx.x * blockDim.x + threadIdx.x;
    if (t < FIN * HID) {            // W0 [256][128] -> W0t [128][256]
        int k = t / HID, n2 = t % HID;
        W0t[n2 * FIN + k] = __float2half(W0[t]);
    }
    if (t < HID * HID) {
        int k = t / HID, n2 = t % HID;
        W1t[n2 * HID + k] = __float2half(W1[t]);
        W2t[n2 * HID + k] = __float2half(W2[t]);
    }
    if (t < HID * OUTD) {
        int k = t / OUTD, n2 = t % OUTD;
        Wlt[n2 * HID + k] = __float2half(Wl[t]);
    }
}

// ---------------------------------------------------------------------------
// CSR build: histogram(+rank) -> block scan -> rank-scatter (4 edges/thread)
// ---------------------------------------------------------------------------
__global__ void zero_cnt_kernel(int* cnt, int n) {
    int i = blockIdx.x * blockDim.x + threadIdx.x;
    if (i < n) cnt[i] = 0;
}
__global__ void hist_kernel(const int* __restrict__ ei, int* cnt, int* rank, int E) {
    int e = (blockIdx.x * blockDim.x + threadIdx.x) * 4;
    if (e + 3 < E) {
        int4 d = *reinterpret_cast<const int4*>(ei + E + e);
        int4 r;
        r.x = atomicAdd(&cnt[d.x], 1);
        r.y = atomicAdd(&cnt[d.y], 1);
        r.z = atomicAdd(&cnt[d.z], 1);
        r.w = atomicAdd(&cnt[d.w], 1);
        *reinterpret_cast<int4*>(rank + e) = r;
    } else {
        for (; e < E; e++) rank[e] = atomicAdd(&cnt[ei[E + e]], 1);
    }
}
__global__ void scan_block_kernel(const int* __restrict__ cnt, int* offs,
                                  int* bsum, int n) {
    __shared__ int sm[SCAN_B];
    int i = blockIdx.x * SCAN_B + threadIdx.x;
    int v = (i < n) ? cnt[i] : 0;
    sm[threadIdx.x] = v;
    __syncthreads();
    #pragma unroll
    for (int o = 1; o < SCAN_B; o <<= 1) {
        int y = (threadIdx.x >= o) ? sm[threadIdx.x - o] : 0;
        __syncthreads();
        sm[threadIdx.x] += y;
        __syncthreads();
    }
    if (i < n) offs[i] = sm[threadIdx.x] - v;
    if (threadIdx.x == SCAN_B - 1) bsum[blockIdx.x] = sm[SCAN_B - 1];
}
__global__ void scan_top_kernel(const int* __restrict__ bsum, int* bbase, int nb) {
    __shared__ int sm[SCAN_B];
    int v = (threadIdx.x < nb) ? bsum[threadIdx.x] : 0;
    sm[threadIdx.x] = v;
    __syncthreads();
    #pragma unroll
    for (int o = 1; o < SCAN_B; o <<= 1) {
        int y = (threadIdx.x >= o) ? sm[threadIdx.x - o] : 0;
        __syncthreads();
        sm[threadIdx.x] += y;
        __syncthreads();
    }
    if (threadIdx.x < nb) bbase[threadIdx.x] = sm[threadIdx.x] - v;
}
__global__ void finalize_offs_kernel(int* offs, const int* __restrict__ bbase,
                                     const int* __restrict__ cnt,
                                     float* dinv, int n) {
    int i = blockIdx.x * blockDim.x + threadIdx.x;
    if (i < n) {
        offs[i] += bbase[i / SCAN_B];
        dinv[i] = rsqrtf((float)(cnt[i] + 1));
    }
}
__global__ void scatter_edges_kernel(const int* __restrict__ ei,
                                     const int* __restrict__ offs,
                                     const int* __restrict__ rank,
                                     int* ssrc, int E) {
    int e = (blockIdx.x * blockDim.x + threadIdx.x) * 4;
    if (e + 3 < E) {
        int4 s = *reinterpret_cast<const int4*>(ei + e);
        int4 d = *reinterpret_cast<const int4*>(ei + E + e);
        int4 r = *reinterpret_cast<const int4*>(rank + e);
        int o0 = offs[d.x], o1 = offs[d.y], o2 = offs[d.z], o3 = offs[d.w];
        ssrc[o0 + r.x] = s.x;
        ssrc[o1 + r.y] = s.y;
        ssrc[o2 + r.z] = s.z;
        ssrc[o3 + r.w] = s.w;
    } else {
        for (; e < E; e++)
            ssrc[offs[ei[E + e]] + rank[e]] = ei[e];
    }
}

// ---------------------------------------------------------------------------
// FP16 tensor-core GEMM core. BK=32 halfs, fp16 A + transposed fp16 W.
//   As[128][40] halfs (pad 40 -> conflict-free), Ws[BN][40] halfs (n-major)
// ---------------------------------------------------------------------------
#define HPAD 40

template<int BN, int K>
struct HCore {
    static constexpr int NTN = (BN / 2) / 8;

    static __device__ __forceinline__
    void loadA(__half (*As)[HPAD], const __half* __restrict__ A,
               int rowBase, int kt, int n, int tid) {
        #pragma unroll
        for (int i = 0; i < 2; i++) {
            int ch  = i * 256 + tid;
            int row = ch >> 2;
            int cin = (ch & 3) * 8;
            int grow = rowBase + row;
            if (grow >= n) grow = n - 1;
            cp_async16(&As[row][cin], A + (size_t)grow * K + kt + cin);
        }
    }
    static __device__ __forceinline__
    void loadW(__half (*Ws)[HPAD], const __half* __restrict__ Wt, int kt, int tid) {
        constexpr int NCH = BN * 4;
        #pragma unroll
        for (int i = 0; i < NCH / 256; i++) {
            int ch  = i * 256 + tid;
            int nn  = ch >> 2;
            int cin = (ch & 3) * 8;
            cp_async16(&Ws[nn][cin], Wt + (size_t)nn * K + kt + cin);
        }
    }
    static __device__ __forceinline__
    void compute(const __half (*As)[HPAD], const __half (*Ws)[HPAD],
                 float acc[2][NTN][4], int m0, int n0, int lane) {
        const int gid = lane >> 2;
        const int tig = lane & 3;
        #pragma unroll
        for (int kk = 0; kk < 32; kk += 16) {
            uint32_t a[2][4];
            #pragma unroll
            for (int mt = 0; mt < 2; mt++) {
                int r = m0 + mt * 16 + gid;
                int c = kk + tig * 2;
                a[mt][0] = *reinterpret_cast<const uint32_t*>(&As[r    ][c    ]);
                a[mt][1] = *reinterpret_cast<const uint32_t*>(&As[r + 8][c    ]);
                a[mt][2] = *reinterpret_cast<const uint32_t*>(&As[r    ][c + 8]);
                a[mt][3] = *reinterpret_cast<const uint32_t*>(&As[r + 8][c + 8]);
            }
            #pragma unroll
            for (int nt = 0; nt < NTN; nt++) {
                int nn = n0 + nt * 8 + gid;
                int c  = kk + tig * 2;
                uint32_t b0 = *reinterpret_cast<const uint32_t*>(&Ws[nn][c    ]);
                uint32_t b1 = *reinterpret_cast<const uint32_t*>(&Ws[nn][c + 8]);
                mma_f16(acc[0][nt], a[0], b0, b1);
                mma_f16(acc[1][nt], a[1], b0, b1);
            }
        }
    }
};

// ---------------------------------------------------------------------------
// Layer-0 GEMM: A fp32 in gmem, converted to fp16 in the loader (LDG+cvt+STS,
// register double-buffered), fp16 MMA. T = x @ W0, fp16 out. K=FIN.
// ---------------------------------------------------------------------------
__global__ void __launch_bounds__(256, 2)
gemm_f16_conv_kernel(const float* __restrict__ A, const __half* __restrict__ Wt,
                     __half* __restrict__ T, int n)
{
    constexpr int BN = HID, K = FIN;
    using C = HCore<BN, K>;
    constexpr int NTN = C::NTN;
    constexpr int NT  = K / 32;     // 8 tiles of 32 k

    __shared__ __half As[2][128][HPAD];
    __shared__ __half Ws[2][BN][HPAD];

    const int tid  = threadIdx.x;
    const int wid  = tid >> 5, lane = tid & 31;
    const int m0   = (wid >> 1) * 32;
    const int n0   = (wid & 1) * (BN / 2);
    const int rowBase = blockIdx.x * 128;

    // A-loader mapping: 1024 float4-chunks per tile (128 rows x 8), 4/thread
    int lrow[4], lcol[4];
    const float* lsrc[4];
    #pragma unroll
    for (int i = 0; i < 4; i++) {
        int ch = i * 256 + tid;
        lrow[i] = ch >> 3;
        lcol[i] = (ch & 7) * 4;
        int grow = rowBase + lrow[i];
        if (grow >= n) grow = n - 1;
        lsrc[i] = A + (size_t)grow * K + lcol[i];
    }

    float acc[2][NTN][4];
    #pragma unroll
    for (int mt = 0; mt < 2; mt++)
        #pragma unroll
        for (int nt = 0; nt < NTN; nt++)
            #pragma unroll
            for (int q = 0; q < 4; q++) acc[mt][nt][q] = 0.0f;

    // prologue: LDG tile 0 into regs, cp.async W tile 0
    float4 rA[4];
    #pragma unroll
    for (int i = 0; i < 4; i++)
        rA[i] = *reinterpret_cast<const float4*>(lsrc[i]);
    C::loadW(Ws[0], Wt, 0, tid);
    cp_commit();

    #pragma unroll 1
    for (int t = 0; t < NT; t++) {
        int cur = t & 1, nxt = cur ^ 1;
        // convert + store current A regs into smem
        #pragma unroll
        for (int i = 0; i < 4; i++) {
            uint2 u;
            __half2* hp = reinterpret_cast<__half2*>(&u);
            hp[0] = __float22half2_rn(make_float2(rA[i].x, rA[i].y));
            hp[1] = __float22half2_rn(make_float2(rA[i].z, rA[i].w));
            *reinterpret_cast<uint2*>(&As[cur][lrow[i]][lcol[i]]) = u;
        }
        // prefetch next tile
        if (t + 1 < NT) {
            #pragma unroll
            for (int i = 0; i < 4; i++)
                rA[i] = *reinterpret_cast<const float4*>(lsrc[i] + (t + 1) * 32);
            C::loadW(Ws[nxt], Wt, (t + 1) * 32, tid);
        }
        cp_commit();
        cp_wait<1>();
        __syncthreads();
        C::compute(As[cur], Ws[cur], acc, m0, n0, lane);
        __syncthreads();
    }

    const int gid = lane >> 2, tig = lane & 3;
    #pragma unroll
    for (int mt = 0; mt < 2; mt++) {
        #pragma unroll
        for (int nt = 0; nt < NTN; nt++) {
            int r = rowBase + m0 + mt * 16 + gid;
            int c = n0 + nt * 8 + tig * 2;
            if (r < n)
                *reinterpret_cast<__half2*>(T + (size_t)r * BN + c) =
                    __float22half2_rn(make_float2(acc[mt][nt][0], acc[mt][nt][1]));
            if (r + 8 < n)
                *reinterpret_cast<__half2*>(T + (size_t)(r + 8) * BN + c) =
                    __float22half2_rn(make_float2(acc[mt][nt][2], acc[mt][nt][3]));
        }
    }
}

// ---------------------------------------------------------------------------
// FP16 GEMM: T = A @ W (A fp16 [n][K], Wt fp16 [BN][K]), fp16 output
// ---------------------------------------------------------------------------
template<int BN, int K>
__global__ void __launch_bounds__(256, 2)
gemm_f16_kernel(const __half* __restrict__ A, const __half* __restrict__ Wt,
                __half* __restrict__ T, int n)
{
    using C = HCore<BN, K>;
    constexpr int NTN = C::NTN;
    constexpr int NT  = K / 32;

    __shared__ __half As[2][128][HPAD];
    __shared__ __half Ws[2][BN][HPAD];

    const int tid  = threadIdx.x;
    const int wid  = tid >> 5, lane = tid & 31;
    const int m0   = (wid >> 1) * 32;
    const int n0   = (wid & 1) * (BN / 2);
    const int rowBase = blockIdx.x * 128;

    float acc[2][NTN][4];
    #pragma unroll
    for (int mt = 0; mt < 2; mt++)
        #pragma unroll
        for (int nt = 0; nt < NTN; nt++)
            #pragma unroll
            for (int q = 0; q < 4; q++) acc[mt][nt][q] = 0.0f;

    C::loadA(As[0], A, rowBase, 0, n, tid);
    C::loadW(Ws[0], Wt, 0, tid);
    cp_commit();

    #pragma unroll 1
    for (int t = 0; t < NT; t++) {
        int cur = t & 1, nxt = cur ^ 1;
        if (t + 1 < NT) {
            C::loadA(As[nxt], A, rowBase, (t + 1) * 32, n, tid);
            C::loadW(Ws[nxt], Wt, (t + 1) * 32, tid);
        }
        cp_commit();
        cp_wait<1>();
        __syncthreads();
        C::compute(As[cur], Ws[cur], acc, m0, n0, lane);
        __syncthreads();
    }

    const int gid = lane >> 2, tig = lane & 3;
    #pragma unroll
    for (int mt = 0; mt < 2; mt++) {
        #pragma unroll
        for (int nt = 0; nt < NTN; nt++) {
            int r = rowBase + m0 + mt * 16 + gid;
            int c = n0 + nt * 8 + tig * 2;
            if (r < n)
                *reinterpret_cast<__half2*>(T + (size_t)r * BN + c) =
                    __float22half2_rn(make_float2(acc[mt][nt][0], acc[mt][nt][1]));
            if (r + 8 < n)
                *reinterpret_cast<__half2*>(T + (size_t)(r + 8) * BN + c) =
                    __float22half2_rn(make_float2(acc[mt][nt][2], acc[mt][nt][3]));
        }
    }
}

// ---------------------------------------------------------------------------
// Gather aggregation: half-warp split, fp16 in, fp16 out.
// ---------------------------------------------------------------------------
__global__ void __launch_bounds__(256)
agg_gather_kernel(const int* __restrict__ ssrc, const int* __restrict__ offs,
                  const int* __restrict__ cnt, const float* __restrict__ dinv,
                  const float* __restrict__ bias, const __half* __restrict__ T,
                  __half* __restrict__ G, int n)
{
    int node = blockIdx.x * 8 + (threadIdx.x >> 5);
    if (node >= n) return;
    int lane = threadIdx.x & 31;
    int l16  = lane & 15;
    int h    = lane >> 4;

    float dv = dinv[node];
    float acc[8];
    if (h == 0) {
        uint4 u = *reinterpret_cast<const uint4*>(T + (size_t)node * HID + l16 * 8);
        const __half2* hp = reinterpret_cast<const __half2*>(&u);
        float4 b0 = *reinterpret_cast<const float4*>(bias + l16 * 8);
        float4 b1 = *reinterpret_cast<const float4*>(bias + l16 * 8 + 4);
        float d2 = dv * dv;
        float2 f0 = __half22float2(hp[0]), f1 = __half22float2(hp[1]);
        float2 f2 = __half22float2(hp[2]), f3 = __half22float2(hp[3]);
        acc[0] = d2 * f0.x + b0.x; acc[1] = d2 * f0.y + b0.y;
        acc[2] = d2 * f1.x + b0.z; acc[3] = d2 * f1.y + b0.w;
        acc[4] = d2 * f2.x + b1.x; acc[5] = d2 * f2.y + b1.y;
        acc[6] = d2 * f3.x + b1.z; acc[7] = d2 * f3.y + b1.w;
    } else {
        #pragma unroll
        for (int j = 0; j < 8; j++) acc[j] = 0.0f;
    }

    int beg = offs[node];
    int deg = cnt[node];
    int e = 0;
    for (; e + 7 < deg; e += 8) {
        int base = beg + e + h;
        int s0 = ssrc[base], s1 = ssrc[base + 2];
        int s2 = ssrc[base + 4], s3 = ssrc[base + 6];
        float n0 = dinv[s0] * dv, n1 = dinv[s1] * dv;
        float n2 = dinv[s2] * dv, n3 = dinv[s3] * dv;
        accum_row8(acc, T, s0, l16, n0);
        accum_row8(acc, T, s1, l16, n1);
        accum_row8(acc, T, s2, l16, n2);
        accum_row8(acc, T, s3, l16, n3);
    }
    for (; e + 1 < deg; e += 2) {
        int s0 = ssrc[beg + e + h];
        accum_row8(acc, T, s0, l16, dinv[s0] * dv);
    }
    if (e < deg && h == 0) {
        int s0 = ssrc[beg + e];
        accum_row8(acc, T, s0, l16, dinv[s0] * dv);
    }

    #pragma unroll
    for (int j = 0; j < 8; j++)
        acc[j] += __shfl_down_sync(0xFFFFFFFFu, acc[j], 16);

    if (h == 0) {
        uint4 u;
        __half2* hp = reinterpret_cast<__half2*>(&u);
        hp[0] = __float22half2_rn(make_float2(acc[0], acc[1]));
        hp[1] = __float22half2_rn(make_float2(acc[2], acc[3]));
        hp[2] = __float22half2_rn(make_float2(acc[4], acc[5]));
        hp[3] = __float22half2_rn(make_float2(acc[6], acc[7]));
        *reinterpret_cast<uint4*>(G + (size_t)node * HID + l16 * 8) = u;
    }
}

// ---------------------------------------------------------------------------
// Final layer FP16 GEMM + fused global max-pool (BN=64)
// ---------------------------------------------------------------------------
__device__ __forceinline__ void atomicMaxF(float* addr, float v) {
    if (v >= 0.0f) atomicMax((int*)addr, __float_as_int(v));
    else           atomicMin((unsigned int*)addr, __float_as_uint(v));
}

__global__ void init_out_kernel(float* out) {
    if (threadIdx.x < OUTD) out[threadIdx.x] = __int_as_float(0xFF800000);
}

__global__ void __launch_bounds__(256, 2)
gemm_max_f16_kernel(const __half* __restrict__ A, const __half* __restrict__ Wt,
                    const float* __restrict__ bias, float* __restrict__ out, int n)
{
    constexpr int BN = OUTD;
    using C = HCore<BN, HID>;
    constexpr int NTN = C::NTN;
    constexpr int NT  = HID / 32;

    __shared__ __half As[2][128][HPAD];
    __shared__ __half Ws[2][BN][HPAD];
    __shared__ float red[OUTD];

    const int tid  = threadIdx.x;
    const int wid  = tid >> 5, lane = tid & 31;
    const int m0   = (wid >> 1) * 32;
    const int n0   = (wid & 1) * (BN / 2);
    const int rowBase = blockIdx.x * 128;

    if (tid < OUTD) red[tid] = __int_as_float(0xFF800000);

    float acc[2][NTN][4];
    #pragma unroll
    for (int mt = 0; mt < 2; mt++)
        #pragma unroll
        for (int nt = 0; nt < NTN; nt++)
            #pragma unroll
            for (int q = 0; q < 4; q++) acc[mt][nt][q] = 0.0f;

    C::loadA(As[0], A, rowBase, 0, n, tid);
    C::loadW(Ws[0], Wt, 0, tid);
    cp_commit();

    #pragma unroll 1
    for (int t = 0; t < NT; t++) {
        int cur = t & 1, nxt = cur ^ 1;
        if (t + 1 < NT) {
            C::loadA(As[nxt], A, rowBase, (t + 1) * 32, n, tid);
            C::loadW(Ws[nxt], Wt, (t + 1) * 32, tid);
        }
        cp_commit();
        cp_wait<1>();
        __syncthreads();
        C::compute(As[cur], Ws[cur], acc, m0, n0, lane);
        __syncthreads();
    }

    const int tig = lane & 3;
    #pragma unroll
    for (int nt = 0; nt < NTN; nt++) {
        int c = n0 + nt * 8 + tig * 2;
        float m0v = fmaxf(fmaxf(acc[0][nt][0], acc[0][nt][2]),
                          fmaxf(acc[1][nt][0], acc[1][nt][2]));
        float m1v = fmaxf(fmaxf(acc[0][nt][1], acc[0][nt][3]),
                          fmaxf(acc[1][nt][1], acc[1][nt][3]));
        atomicMaxF(&red[c],     m0v + bias[c]);
        atomicMaxF(&red[c + 1], m1v + bias[c + 1]);
    }
    __syncthreads();
    if (tid < OUTD) atomicMaxF(&out[tid], red[tid]);
}

// ---------------------------------------------------------------------------
// Launch
// ---------------------------------------------------------------------------
extern "C" void kernel_launch(void* const* d_in, const int* in_sizes, int n_in,
                              void* d_out, int out_size)
{
    const float* x    = (const float*)d_in[0];
    const int*   ei   = (const int*)  d_in[1];
    const float* W0   = (const float*)d_in[3];
    const float* b0   = (const float*)d_in[4];
    const float* W1   = (const float*)d_in[5];
    const float* b1   = (const float*)d_in[6];
    const float* W2   = (const float*)d_in[7];
    const float* b2   = (const float*)d_in[8];
    const float* Wlin = (const float*)d_in[9];
    const float* blin = (const float*)d_in[10];
    float* out = (float*)d_out;

    const int n = in_sizes[0] / FIN;
    const int E = in_sizes[1] / 2;

    __half *pT, *pG1, *pG2, *pW0t, *pW1t, *pW2t, *pWlt;
    float *pD;
    int *pCnt, *pOffs, *pBs, *pBb, *pSrc, *pRank;
    cudaGetSymbolAddress((void**)&pT, g_T);
    cudaGetSymbolAddress((void**)&pG1, g_G1);
    cudaGetSymbolAddress((void**)&pG2, g_G2);
    cudaGetSymbolAddress((void**)&pW0t, g_W0t);
    cudaGetSymbolAddress((void**)&pW1t, g_W1t);
    cudaGetSymbolAddress((void**)&pW2t, g_W2t);
    cudaGetSymbolAddress((void**)&pWlt, g_Wlt);
    cudaGetSymbolAddress((void**)&pD, g_dinv);
    cudaGetSymbolAddress((void**)&pCnt, g_cnt);
    cudaGetSymbolAddress((void**)&pOffs, g_offs);
    cudaGetSymbolAddress((void**)&pBs, g_bsum);
    cudaGetSymbolAddress((void**)&pBb, g_bbase);
    cudaGetSymbolAddress((void**)&pSrc, g_ssrc);
    cudaGetSymbolAddress((void**)&pRank, g_rank);

    const int nodeBlocks = (n + 255) / 256;
    const int edge4Blocks = (E / 4 + 255) / 256;
    const int gemmBlocks = (n + 127) / 128;
    const int scanBlocks = (n + SCAN_B - 1) / SCAN_B;
    const int aggBlocks  = (n + 7) / 8;

    // weight conversion (covers FIN*HID threads for W0t)
    convert_w_kernel<<<(FIN * HID + 255) / 256, 256>>>(W0, W1, W2, Wlin,
                                                       pW0t, pW1t, pW2t, pWlt);

    // CSR build + normalization
    zero_cnt_kernel<<<nodeBlocks, 256>>>(pCnt, n);
    hist_kernel<<<edge4Blocks, 256>>>(ei, pCnt, pRank, E);
    scan_block_kernel<<<scanBlocks, SCAN_B>>>(pCnt, pOffs, pBs, n);
    scan_top_kernel<<<1, SCAN_B>>>(pBs, pBb, scanBlocks);
    finalize_offs_kernel<<<nodeBlocks, 256>>>(pOffs, pBb, pCnt, pD, n);
    scatter_edges_kernel<<<edge4Blocks, 256>>>(ei, pOffs, pRank, pSrc, E);

    // layer 0 (fp16 MMA, fused fp32->fp16 A conversion)
    gemm_f16_conv_kernel<<<gemmBlocks, 256>>>(x, pW0t, pT, n);
    agg_gather_kernel<<<aggBlocks, 256>>>(pSrc, pOffs, pCnt, pD, b0, pT, pG1, n);
    // layer 1 (fp16)
    gemm_f16_kernel<HID, HID><<<gemmBlocks, 256>>>(pG1, pW1t, pT, n);
    agg_gather_kernel<<<aggBlocks, 256>>>(pSrc, pOffs, pCnt, pD, b1, pT, pG2, n);
    // layer 2 (fp16)
    gemm_f16_kernel<HID, HID><<<gemmBlocks, 256>>>(pG2, pW2t, pT, n);
    agg_gather_kernel<<<aggBlocks, 256>>>(pSrc, pOffs, pCnt, pD, b2, pT, pG1, n);

    // final (fp16 + max-pool)
    init_out_kernel<<<1, 64>>>(out);
    gemm_max_f16_kernel<<<gemmBlocks, 256>>>(pG1, pWlt, blin, out, n);
}

// round 15
// speedup vs baseline: 1.1297x; 1.0240x over previous
#include <cuda_runtime.h>
#include <cuda_fp16.h>
#include <cstdint>
#include <cstddef>

#define FIN   256
#define HID   128
#define OUTD  64
#define MAXN  50176
#define MAXE  800000
#define SCAN_B 256

__device__ __align__(16) __half g_T[(size_t)MAXN * HID];   // post-GEMM features
__device__ __align__(16) __half g_G1[(size_t)MAXN * HID];  // aggregated (fp16)
__device__ __align__(16) __half g_G2[(size_t)MAXN * HID];
__device__ __align__(16) __half g_W0t[HID * FIN];          // transposed fp16 weights
__device__ __align__(16) __half g_W1t[HID * HID];
__device__ __align__(16) __half g_W2t[HID * HID];
__device__ __align__(16) __half g_Wlt[OUTD * HID];
__device__ float  g_dinv[MAXN];
__device__ int    g_cnt[MAXN];
__device__ int    g_offs[MAXN];
__device__ int    g_scan_ctr;
__device__ __align__(16) int g_ssrc[MAXE];
__device__ __align__(16) int g_rank[MAXE];

// ---------------------------------------------------------------------------
// PTX helpers
// ---------------------------------------------------------------------------
__device__ __forceinline__ void cp_async16(void* smem_dst, const void* gmem_src) {
    uint32_t s = (uint32_t)__cvta_generic_to_shared(smem_dst);
    asm volatile("cp.async.cg.shared.global [%0], [%1], 16;\n" :: "r"(s), "l"(gmem_src));
}
__device__ __forceinline__ void cp_commit() {
    asm volatile("cp.async.commit_group;\n");
}
template<int N>
__device__ __forceinline__ void cp_wait() {
    asm volatile("cp.async.wait_group %0;\n" :: "n"(N));
}
__device__ __forceinline__ void mma_f16(float c[4], const uint32_t a[4],
                                        uint32_t b0, uint32_t b1) {
    asm volatile(
        "mma.sync.aligned.m16n8k16.row.col.f32.f16.f16.f32 "
        "{%0,%1,%2,%3}, {%4,%5,%6,%7}, {%8,%9}, {%0,%1,%2,%3};"
        : "+f"(c[0]), "+f"(c[1]), "+f"(c[2]), "+f"(c[3])
        : "r"(a[0]), "r"(a[1]), "r"(a[2]), "r"(a[3]), "r"(b0), "r"(b1));
}
// accumulate 8 halfs (one uint4) scaled by nr into acc[8]
__device__ __forceinline__ void accum_row8(float acc[8], const __half* __restrict__ T,
                                           int row, int l16, float nr) {
    uint4 u = *reinterpret_cast<const uint4*>(T + (size_t)row * HID + l16 * 8);
    const __half2* hp = reinterpret_cast<const __half2*>(&u);
    #pragma unroll
    for (int q = 0; q < 4; q++) {
        float2 f = __half22float2(hp[q]);
        acc[2*q]   += nr * f.x;
        acc[2*q+1] += nr * f.y;
    }
}

// ---------------------------------------------------------------------------
// Prep: weight converts + zero cnt + out init + scan-counter reset
// ---------------------------------------------------------------------------
__global__ void prep_kernel(const float* __restrict__ W0,
                            const float* __restrict__ W1,
                            const float* __restrict__ W2,
                            const float* __restrict__ Wl,
                            __half* __restrict__ W0t,
                            __half* __restrict__ W1t,
                            __half* __restrict__ W2t,
                            __half* __restrict__ Wlt,
                            int* __restrict__ cnt, int* __restrict__ ctr,
                            float* __restrict__ out, int n) {
    int t = blockIdx.x * blockDim.x + threadIdx.x;
    if (t < n) cnt[t] = 0;
    if (t == 0) *ctr = 0;
    if (t < OUTD) out[t] = __int_as_float(0xFF800000);
    if (t < FIN * HID) {            // W0 [256][128] -> W0t [128][256]
        int k = t / HID, n2 = t % HID;
        W0t[n2 * FIN + k] = __float2half(W0[t]);
    }
    if (t < HID * HID) {
        int k = t / HID, n2 = t % HID;
        W1t[n2 * HID + k] = __float2half(W1[t]);
        W2t[n2 * HID + k] = __float2half(W2[t]);
    }
    if (t < HID * OUTD) {
        int k = t / OUTD, n2 = t % OUTD;
        Wlt[n2 * HID + k] = __float2half(Wl[t]);
    }
}

// ---------------------------------------------------------------------------
// CSR build: histogram(+rank) -> fused scan (+dinv) -> rank-scatter
// ---------------------------------------------------------------------------
__global__ void hist_kernel(const int* __restrict__ ei, int* cnt, int* rank, int E) {
    int e = (blockIdx.x * blockDim.x + threadIdx.x) * 4;
    if (e + 3 < E) {
        int4 d = *reinterpret_cast<const int4*>(ei + E + e);
        int4 r;
        r.x = atomicAdd(&cnt[d.x], 1);
        r.y = atomicAdd(&cnt[d.y], 1);
        r.z = atomicAdd(&cnt[d.z], 1);
        r.w = atomicAdd(&cnt[d.w], 1);
        *reinterpret_cast<int4*>(rank + e) = r;
    } else {
        for (; e < E; e++) rank[e] = atomicAdd(&cnt[ei[E + e]], 1);
    }
}

// Block-local scan + atomic block base; writes offs and dinv in one pass.
// Block bases are allocated in arbitrary order — harmless: offs is used
// consistently by scatter and gather, only the physical CSR layout varies.
__global__ void scan_fused_kernel(const int* __restrict__ cnt, int* offs,
                                  float* dinv, int* ctr, int n) {
    __shared__ int sm[SCAN_B];
    __shared__ int s_base;
    int i = blockIdx.x * SCAN_B + threadIdx.x;
    int v = (i < n) ? cnt[i] : 0;
    sm[threadIdx.x] = v;
    __syncthreads();
    #pragma unroll
    for (int o = 1; o < SCAN_B; o <<= 1) {
        int y = (threadIdx.x >= o) ? sm[threadIdx.x - o] : 0;
        __syncthreads();
        sm[threadIdx.x] += y;
        __syncthreads();
    }
    if (threadIdx.x == SCAN_B - 1)
        s_base = atomicAdd(ctr, sm[SCAN_B - 1]);
    __syncthreads();
    if (i < n) {
        offs[i] = s_base + sm[threadIdx.x] - v;
        dinv[i] = rsqrtf((float)(v + 1));
    }
}

__global__ void scatter_edges_kernel(const int* __restrict__ ei,
                                     const int* __restrict__ offs,
                                     const int* __restrict__ rank,
                                     int* ssrc, int E) {
    int e = (blockIdx.x * blockDim.x + threadIdx.x) * 4;
    if (e + 3 < E) {
        int4 s = *reinterpret_cast<const int4*>(ei + e);
        int4 d = *reinterpret_cast<const int4*>(ei + E + e);
        int4 r = *reinterpret_cast<const int4*>(rank + e);
        int o0 = offs[d.x], o1 = offs[d.y], o2 = offs[d.z], o3 = offs[d.w];
        ssrc[o0 + r.x] = s.x;
        ssrc[o1 + r.y] = s.y;
        ssrc[o2 + r.z] = s.z;
        ssrc[o3 + r.w] = s.w;
    } else {
        for (; e < E; e++)
            ssrc[offs[ei[E + e]] + rank[e]] = ei[e];
    }
}

// ---------------------------------------------------------------------------
// FP16 tensor-core GEMM core. BK=32 halfs, fp16 A + transposed fp16 W.
// ---------------------------------------------------------------------------
#define HPAD 40

template<int BN, int K>
struct HCore {
    static constexpr int NTN = (BN / 2) / 8;

    static __device__ __forceinline__
    void loadA(__half (*As)[HPAD], const __half* __restrict__ A,
               int rowBase, int kt, int n, int tid) {
        #pragma unroll
        for (int i = 0; i < 2; i++) {
            int ch  = i * 256 + tid;
            int row = ch >> 2;
            int cin = (ch & 3) * 8;
            int grow = rowBase + row;
            if (grow >= n) grow = n - 1;
            cp_async16(&As[row][cin], A + (size_t)grow * K + kt + cin);
        }
    }
    static __device__ __forceinline__
    void loadW(__half (*Ws)[HPAD], const __half* __restrict__ Wt, int kt, int tid) {
        constexpr int NCH = BN * 4;
        #pragma unroll
        for (int i = 0; i < NCH / 256; i++) {
            int ch  = i * 256 + tid;
            int nn  = ch >> 2;
            int cin = (ch & 3) * 8;
            cp_async16(&Ws[nn][cin], Wt + (size_t)nn * K + kt + cin);
        }
    }
    static __device__ __forceinline__
    void compute(const __half (*As)[HPAD], const __half (*Ws)[HPAD],
                 float acc[2][NTN][4], int m0, int n0, int lane) {
        const int gid = lane >> 2;
        const int tig = lane & 3;
        #pragma unroll
        for (int kk = 0; kk < 32; kk += 16) {
            uint32_t a[2][4];
            #pragma unroll
            for (int mt = 0; mt < 2; mt++) {
                int r = m0 + mt * 16 + gid;
                int c = kk + tig * 2;
                a[mt][0] = *reinterpret_cast<const uint32_t*>(&As[r    ][c    ]);
                a[mt][1] = *reinterpret_cast<const uint32_t*>(&As[r + 8][c    ]);
                a[mt][2] = *reinterpret_cast<const uint32_t*>(&As[r    ][c + 8]);
                a[mt][3] = *reinterpret_cast<const uint32_t*>(&As[r + 8][c + 8]);
            }
            #pragma unroll
            for (int nt = 0; nt < NTN; nt++) {
                int nn = n0 + nt * 8 + gid;
                int c  = kk + tig * 2;
                uint32_t b0 = *reinterpret_cast<const uint32_t*>(&Ws[nn][c    ]);
                uint32_t b1 = *reinterpret_cast<const uint32_t*>(&Ws[nn][c + 8]);
                mma_f16(acc[0][nt], a[0], b0, b1);
                mma_f16(acc[1][nt], a[1], b0, b1);
            }
        }
    }
};

// ---------------------------------------------------------------------------
// Layer-0 GEMM: A fp32 in gmem, converted to fp16 in the loader (LDG+cvt+STS,
// register double-buffered), fp16 MMA. T = x @ W0, fp16 out. K=FIN.
// ---------------------------------------------------------------------------
__global__ void __launch_bounds__(256, 2)
gemm_f16_conv_kernel(const float* __restrict__ A, const __half* __restrict__ Wt,
                     __half* __restrict__ T, int n)
{
    constexpr int BN = HID, K = FIN;
    using C = HCore<BN, K>;
    constexpr int NTN = C::NTN;
    constexpr int NT  = K / 32;

    __shared__ __half As[2][128][HPAD];
    __shared__ __half Ws[2][BN][HPAD];

    const int tid  = threadIdx.x;
    const int wid  = tid >> 5, lane = tid & 31;
    const int m0   = (wid >> 1) * 32;
    const int n0   = (wid & 1) * (BN / 2);
    const int rowBase = blockIdx.x * 128;

    int lrow[4], lcol[4];
    const float* lsrc[4];
    #pragma unroll
    for (int i = 0; i < 4; i++) {
        int ch = i * 256 + tid;
        lrow[i] = ch >> 3;
        lcol[i] = (ch & 7) * 4;
        int grow = rowBase + lrow[i];
        if (grow >= n) grow = n - 1;
        lsrc[i] = A + (size_t)grow * K + lcol[i];
    }

    float acc[2][NTN][4];
    #pragma unroll
    for (int mt = 0; mt < 2; mt++)
        #pragma unroll
        for (int nt = 0; nt < NTN; nt++)
            #pragma unroll
            for (int q = 0; q < 4; q++) acc[mt][nt][q] = 0.0f;

    float4 rA[4];
    #pragma unroll
    for (int i = 0; i < 4; i++)
        rA[i] = *reinterpret_cast<const float4*>(lsrc[i]);
    C::loadW(Ws[0], Wt, 0, tid);
    cp_commit();

    #pragma unroll 1
    for (int t = 0; t < NT; t++) {
        int cur = t & 1, nxt = cur ^ 1;
        #pragma unroll
        for (int i = 0; i < 4; i++) {
            uint2 u;
            __half2* hp = reinterpret_cast<__half2*>(&u);
            hp[0] = __float22half2_rn(make_float2(rA[i].x, rA[i].y));
            hp[1] = __float22half2_rn(make_float2(rA[i].z, rA[i].w));
            *reinterpret_cast<uint2*>(&As[cur][lrow[i]][lcol[i]]) = u;
        }
        if (t + 1 < NT) {
            #pragma unroll
            for (int i = 0; i < 4; i++)
                rA[i] = *reinterpret_cast<const float4*>(lsrc[i] + (t + 1) * 32);
            C::loadW(Ws[nxt], Wt, (t + 1) * 32, tid);
        }
        cp_commit();
        cp_wait<1>();
        __syncthreads();
        C::compute(As[cur], Ws[cur], acc, m0, n0, lane);
        __syncthreads();
    }

    const int gid = lane >> 2, tig = lane & 3;
    #pragma unroll
    for (int mt = 0; mt < 2; mt++) {
        #pragma unroll
        for (int nt = 0; nt < NTN; nt++) {
            int r = rowBase + m0 + mt * 16 + gid;
            int c = n0 + nt * 8 + tig * 2;
            if (r < n)
                *reinterpret_cast<__half2*>(T + (size_t)r * BN + c) =
                    __float22half2_rn(make_float2(acc[mt][nt][0], acc[mt][nt][1]));
            if (r + 8 < n)
                *reinterpret_cast<__half2*>(T + (size_t)(r + 8) * BN + c) =
                    __float22half2_rn(make_float2(acc[mt][nt][2], acc[mt][nt][3]));
        }
    }
}

// ---------------------------------------------------------------------------
// FP16 GEMM: T = A @ W (A fp16 [n][K], Wt fp16 [BN][K]), fp16 output
// ---------------------------------------------------------------------------
template<int BN, int K>
__global__ void __launch_bounds__(256, 2)
gemm_f16_kernel(const __half* __restrict__ A, const __half* __restrict__ Wt,
                __half* __restrict__ T, int n)
{
    using C = HCore<BN, K>;
    constexpr int NTN = C::NTN;
    constexpr int NT  = K / 32;

    __shared__ __half As[2][128][HPAD];
    __shared__ __half Ws[2][BN][HPAD];

    const int tid  = threadIdx.x;
    const int wid  = tid >> 5, lane = tid & 31;
    const int m0   = (wid >> 1) * 32;
    const int n0   = (wid & 1) * (BN / 2);
    const int rowBase = blockIdx.x * 128;

    float acc[2][NTN][4];
    #pragma unroll
    for (int mt = 0; mt < 2; mt++)
        #pragma unroll
        for (int nt = 0; nt < NTN; nt++)
            #pragma unroll
            for (int q = 0; q < 4; q++) acc[mt][nt][q] = 0.0f;

    C::loadA(As[0], A, rowBase, 0, n, tid);
    C::loadW(Ws[0], Wt, 0, tid);
    cp_commit();

    #pragma unroll 1
    for (int t = 0; t < NT; t++) {
        int cur = t & 1, nxt = cur ^ 1;
        if (t + 1 < NT) {
            C::loadA(As[nxt], A, rowBase, (t + 1) * 32, n, tid);
            C::loadW(Ws[nxt], Wt, (t + 1) * 32, tid);
        }
        cp_commit();
        cp_wait<1>();
        __syncthreads();
        C::compute(As[cur], Ws[cur], acc, m0, n0, lane);
        __syncthreads();
    }

    const int gid = lane >> 2, tig = lane & 3;
    #pragma unroll
    for (int mt = 0; mt < 2; mt++) {
        #pragma unroll
        for (int nt = 0; nt < NTN; nt++) {
            int r = rowBase + m0 + mt * 16 + gid;
            int c = n0 + nt * 8 + tig * 2;
            if (r < n)
                *reinterpret_cast<__half2*>(T + (size_t)r * BN + c) =
                    __float22half2_rn(make_float2(acc[mt][nt][0], acc[mt][nt][1]));
            if (r + 8 < n)
                *reinterpret_cast<__half2*>(T + (size_t)(r + 8) * BN + c) =
                    __float22half2_rn(make_float2(acc[mt][nt][2], acc[mt][nt][3]));
        }
    }
}

// ---------------------------------------------------------------------------
// Gather aggregation: half-warp split, fp16 in, fp16 out.
// ---------------------------------------------------------------------------
__global__ void __launch_bounds__(256)
agg_gather_kernel(const int* __restrict__ ssrc, const int* __restrict__ offs,
                  const int* __restrict__ cnt, const float* __restrict__ dinv,
                  const float* __restrict__ bias, const __half* __restrict__ T,
                  __half* __restrict__ G, int n)
{
    int node = blockIdx.x * 8 + (threadIdx.x >> 5);
    if (node >= n) return;
    int lane = threadIdx.x & 31;
    int l16  = lane & 15;
    int h    = lane >> 4;

    float dv = dinv[node];
    float acc[8];
    if (h == 0) {
        uint4 u = *reinterpret_cast<const uint4*>(T + (size_t)node * HID + l16 * 8);
        const __half2* hp = reinterpret_cast<const __half2*>(&u);
        float4 b0 = *reinterpret_cast<const float4*>(bias + l16 * 8);
        float4 b1 = *reinterpret_cast<const float4*>(bias + l16 * 8 + 4);
        float d2 = dv * dv;
        float2 f0 = __half22float2(hp[0]), f1 = __half22float2(hp[1]);
        float2 f2 = __half22float2(hp[2]), f3 = __half22float2(hp[3]);
        acc[0] = d2 * f0.x + b0.x; acc[1] = d2 * f0.y + b0.y;
        acc[2] = d2 * f1.x + b0.z; acc[3] = d2 * f1.y + b0.w;
        acc[4] = d2 * f2.x + b1.x; acc[5] = d2 * f2.y + b1.y;
        acc[6] = d2 * f3.x + b1.z; acc[7] = d2 * f3.y + b1.w;
    } else {
        #pragma unroll
        for (int j = 0; j < 8; j++) acc[j] = 0.0f;
    }

    int beg = offs[node];
    int deg = cnt[node];
    int e = 0;
    for (; e + 7 < deg; e += 8) {
        int base = beg + e + h;
        int s0 = ssrc[base], s1 = ssrc[base + 2];
        int s2 = ssrc[base + 4], s3 = ssrc[base + 6];
        float n0 = dinv[s0] * dv, n1 = dinv[s1] * dv;
        float n2 = dinv[s2] * dv, n3 = dinv[s3] * dv;
        accum_row8(acc, T, s0, l16, n0);
        accum_row8(acc, T, s1, l16, n1);
        accum_row8(acc, T, s2, l16, n2);
        accum_row8(acc, T, s3, l16, n3);
    }
    for (; e + 1 < deg; e += 2) {
        int s0 = ssrc[beg + e + h];
        accum_row8(acc, T, s0, l16, dinv[s0] * dv);
    }
    if (e < deg && h == 0) {
        int s0 = ssrc[beg + e];
        accum_row8(acc, T, s0, l16, dinv[s0] * dv);
    }

    #pragma unroll
    for (int j = 0; j < 8; j++)
        acc[j] += __shfl_down_sync(0xFFFFFFFFu, acc[j], 16);

    if (h == 0) {
        uint4 u;
        __half2* hp = reinterpret_cast<__half2*>(&u);
        hp[0] = __float22half2_rn(make_float2(acc[0], acc[1]));
        hp[1] = __float22half2_rn(make_float2(acc[2], acc[3]));
        hp[2] = __float22half2_rn(make_float2(acc[4], acc[5]));
        hp[3] = __float22half2_rn(make_float2(acc[6], acc[7]));
        *reinterpret_cast<uint4*>(G + (size_t)node * HID + l16 * 8) = u;
    }
}

// ---------------------------------------------------------------------------
// Final layer FP16 GEMM + fused global max-pool (BN=64)
// ---------------------------------------------------------------------------
__device__ __forceinline__ void atomicMaxF(float* addr, float v) {
    if (v >= 0.0f) atomicMax((int*)addr, __float_as_int(v));
    else           atomicMin((unsigned int*)addr, __float_as_uint(v));
}

__global__ void __launch_bounds__(256, 2)
gemm_max_f16_kernel(const __half* __restrict__ A, const __half* __restrict__ Wt,
                    const float* __restrict__ bias, float* __restrict__ out, int n)
{
    constexpr int BN = OUTD;
    using C = HCore<BN, HID>;
    constexpr int NTN = C::NTN;
    constexpr int NT  = HID / 32;

    __shared__ __half As[2][128][HPAD];
    __shared__ __half Ws[2][BN][HPAD];
    __shared__ float red[OUTD];

    const int tid  = threadIdx.x;
    const int wid  = tid >> 5, lane = tid & 31;
    const int m0   = (wid >> 1) * 32;
    const int n0   = (wid & 1) * (BN / 2);
    const int rowBase = blockIdx.x * 128;

    if (tid < OUTD) red[tid] = __int_as_float(0xFF800000);

    float acc[2][NTN][4];
    #pragma unroll
    for (int mt = 0; mt < 2; mt++)
        #pragma unroll
        for (int nt = 0; nt < NTN; nt++)
            #pragma unroll
            for (int q = 0; q < 4; q++) acc[mt][nt][q] = 0.0f;

    C::loadA(As[0], A, rowBase, 0, n, tid);
    C::loadW(Ws[0], Wt, 0, tid);
    cp_commit();

    #pragma unroll 1
    for (int t = 0; t < NT; t++) {
        int cur = t & 1, nxt = cur ^ 1;
        if (t + 1 < NT) {
            C::loadA(As[nxt], A, rowBase, (t + 1) * 32, n, tid);
            C::loadW(Ws[nxt], Wt, (t + 1) * 32, tid);
        }
        cp_commit();
        cp_wait<1>();
        __syncthreads();
        C::compute(As[cur], Ws[cur], acc, m0, n0, lane);
        __syncthreads();
    }

    const int tig = lane & 3;
    #pragma unroll
    for (int nt = 0; nt < NTN; nt++) {
        int c = n0 + nt * 8 + tig * 2;
        float m0v = fmaxf(fmaxf(acc[0][nt][0], acc[0][nt][2]),
                          fmaxf(acc[1][nt][0], acc[1][nt][2]));
        float m1v = fmaxf(fmaxf(acc[0][nt][1], acc[0][nt][3]),
                          fmaxf(acc[1][nt][1], acc[1][nt][3]));
        atomicMaxF(&red[c],     m0v + bias[c]);
        atomicMaxF(&red[c + 1], m1v + bias[c + 1]);
    }
    __syncthreads();
    if (tid < OUTD) atomicMaxF(&out[tid], red[tid]);
}

// ---------------------------------------------------------------------------
// Launch
// ---------------------------------------------------------------------------
extern "C" void kernel_launch(void* const* d_in, const int* in_sizes, int n_in,
                              void* d_out, int out_size)
{
    const float* x    = (const float*)d_in[0];
    const int*   ei   = (const int*)  d_in[1];
    const float* W0   = (const float*)d_in[3];
    const float* b0   = (const float*)d_in[4];
    const float* W1   = (const float*)d_in[5];
    const float* b1   = (const float*)d_in[6];
    const float* W2   = (const float*)d_in[7];
    const float* b2   = (const float*)d_in[8];
    const float* Wlin = (const float*)d_in[9];
    const float* blin = (const float*)d_in[10];
    float* out = (float*)d_out;

    const int n = in_sizes[0] / FIN;
    const int E = in_sizes[1] / 2;

    __half *pT, *pG1, *pG2, *pW0t, *pW1t, *pW2t, *pWlt;
    float *pD;
    int *pCnt, *pOffs, *pCtr, *pSrc, *pRank;
    cudaGetSymbolAddress((void**)&pT, g_T);
    cudaGetSymbolAddress((void**)&pG1, g_G1);
    cudaGetSymbolAddress((void**)&pG2, g_G2);
    cudaGetSymbolAddress((void**)&pW0t, g_W0t);
    cudaGetSymbolAddress((void**)&pW1t, g_W1t);
    cudaGetSymbolAddress((void**)&pW2t, g_W2t);
    cudaGetSymbolAddress((void**)&pWlt, g_Wlt);
    cudaGetSymbolAddress((void**)&pD, g_dinv);
    cudaGetSymbolAddress((void**)&pCnt, g_cnt);
    cudaGetSymbolAddress((void**)&pOffs, g_offs);
    cudaGetSymbolAddress((void**)&pCtr, g_scan_ctr);
    cudaGetSymbolAddress((void**)&pSrc, g_ssrc);
    cudaGetSymbolAddress((void**)&pRank, g_rank);

    const int prepN = (n > FIN * HID) ? n : FIN * HID;
    const int prepBlocks = (prepN + 255) / 256;
    const int edge4Blocks = (E / 4 + 255) / 256;
    const int gemmBlocks = (n + 127) / 128;
    const int scanBlocks = (n + SCAN_B - 1) / SCAN_B;
    const int aggBlocks  = (n + 7) / 8;

    // prologue: weight converts + zero cnt + out init + counter reset
    prep_kernel<<<prepBlocks, 256>>>(W0, W1, W2, Wlin, pW0t, pW1t, pW2t, pWlt,
                                     pCnt, pCtr, out, n);

    // CSR build + normalization
    hist_kernel<<<edge4Blocks, 256>>>(ei, pCnt, pRank, E);
    scan_fused_kernel<<<scanBlocks, SCAN_B>>>(pCnt, pOffs, pD, pCtr, n);
    scatter_edges_kernel<<<edge4Blocks, 256>>>(ei, pOffs, pRank, pSrc, E);

    // layer 0 (fp16 MMA, fused fp32->fp16 A conversion)
    gemm_f16_conv_kernel<<<gemmBlocks, 256>>>(x, pW0t, pT, n);
    agg_gather_kernel<<<aggBlocks, 256>>>(pSrc, pOffs, pCnt, pD, b0, pT, pG1, n);
    // layer 1 (fp16)
    gemm_f16_kernel<HID, HID><<<gemmBlocks, 256>>>(pG1, pW1t, pT, n);
    agg_gather_kernel<<<aggBlocks, 256>>>(pSrc, pOffs, pCnt, pD, b1, pT, pG2, n);
    // layer 2 (fp16)
    gemm_f16_kernel<HID, HID><<<gemmBlocks, 256>>>(pG2, pW2t, pT, n);
    agg_gather_kernel<<<aggBlocks, 256>>>(pSrc, pOffs, pCnt, pD, b2, pT, pG1, n);

    // final (fp16 + max-pool)
    gemm_max_f16_kernel<<<gemmBlocks, 256>>>(pG1, pWlt, blin, out, n);
}